// round 8
// baseline (speedup 1.0000x reference)
#include <cuda_runtime.h>
#include <cuda_bf16.h>
#include <math.h>
#include <stdint.h>

// Problem dims (fixed by the dataset)
#define B_   2
#define T_   2048
#define C_   1024
#define H_   16
#define HD_  64
#define C3_  (3*C_)
#define M_   (B_*T_)          // 4096 rows

// ---------------- scratch (no cudaMalloc allowed) ----------------
__device__ __nv_bfloat16 g_qkv_hi[(size_t)M_ * C3_];
__device__ __nv_bfloat16 g_qkv_lo[(size_t)M_ * C3_];
__device__ __nv_bfloat16 g_x_hi[(size_t)M_ * C_];
__device__ __nv_bfloat16 g_x_lo[(size_t)M_ * C_];
__device__ __nv_bfloat16 g_y_hi[(size_t)M_ * C_];
__device__ __nv_bfloat16 g_y_lo[(size_t)M_ * C_];
__device__ __nv_bfloat16 g_wqkvT_hi[(size_t)C3_ * C_];  // [N=3C][K=C]
__device__ __nv_bfloat16 g_wqkvT_lo[(size_t)C3_ * C_];
__device__ __nv_bfloat16 g_woutT_hi[(size_t)C_ * C_];   // [N=C][K=C]
__device__ __nv_bfloat16 g_woutT_lo[(size_t)C_ * C_];
__device__ int g_ctr[2];                                // persistent-GEMM tile counters

// ---------------- helpers ----------------
__device__ __forceinline__ uint32_t smem_u32(const void* p) {
    return (uint32_t)__cvta_generic_to_shared(p);
}
__device__ __forceinline__ void cp_async16(void* s, const void* g) {
    asm volatile("cp.async.cg.shared.global [%0], [%1], 16;\n"
                 :: "r"(smem_u32(s)), "l"(g));
}
__device__ __forceinline__ void cp_commit() {
    asm volatile("cp.async.commit_group;\n" ::);
}
__device__ __forceinline__ void cp_wait0() {
    asm volatile("cp.async.wait_group 0;\n" ::);
}
__device__ __forceinline__ void mma_bf16(float* d, const uint32_t* a, const uint32_t* b) {
    asm volatile(
        "mma.sync.aligned.m16n8k16.row.col.f32.bf16.bf16.f32 "
        "{%0,%1,%2,%3}, {%4,%5,%6,%7}, {%8,%9}, {%0,%1,%2,%3};\n"
        : "+f"(d[0]), "+f"(d[1]), "+f"(d[2]), "+f"(d[3])
        : "r"(a[0]), "r"(a[1]), "r"(a[2]), "r"(a[3]),
          "r"(b[0]), "r"(b[1]));
}
__device__ __forceinline__ void ldsm_x4(uint32_t* r, uint32_t addr) {
    asm volatile("ldmatrix.sync.aligned.m8n8.x4.shared.b16 {%0,%1,%2,%3}, [%4];"
                 : "=r"(r[0]), "=r"(r[1]), "=r"(r[2]), "=r"(r[3])
                 : "r"(addr));
}
__device__ __forceinline__ void ldsm_x4_trans(uint32_t* r, uint32_t addr) {
    asm volatile("ldmatrix.sync.aligned.m8n8.x4.trans.shared.b16 {%0,%1,%2,%3}, [%4];"
                 : "=r"(r[0]), "=r"(r[1]), "=r"(r[2]), "=r"(r[3])
                 : "r"(addr));
}
__device__ __forceinline__ uint32_t pack_bf16x2(float lo, float hi) {
    uint32_t r;
    asm("cvt.rn.bf16x2.f32 %0, %1, %2;" : "=r"(r) : "f"(hi), "f"(lo));
    return r;
}
__device__ __forceinline__ uint32_t pack_hi_pair(float a, float b,
                                                 float& ra, float& rb) {
    uint32_t w = pack_bf16x2(a, b);
    __nv_bfloat162 h = *reinterpret_cast<__nv_bfloat162*>(&w);
    ra = a - __bfloat162float(h.x);
    rb = b - __bfloat162float(h.y);
    return w;
}

// ---------------- prep kernels ----------------
__global__ void split_f32_kernel(const float* __restrict__ src,
                                 __nv_bfloat16* __restrict__ hi,
                                 __nv_bfloat16* __restrict__ lo, int n)
{
    if (blockIdx.x == 0 && threadIdx.x == 0) {   // reset persistent-GEMM counters
        g_ctr[0] = 0;
        g_ctr[1] = 0;
    }
    int i = blockIdx.x * blockDim.x + threadIdx.x;
    int stride = gridDim.x * blockDim.x;
    for (; i < n; i += stride) {
        float v = src[i];
        __nv_bfloat16 h = __float2bfloat16(v);
        hi[i] = h;
        lo[i] = __float2bfloat16(v - __bfloat162float(h));
    }
}

__global__ void split_transpose_kernel(const float* __restrict__ src,
                                       __nv_bfloat16* __restrict__ hi,
                                       __nv_bfloat16* __restrict__ lo,
                                       int K, int N)
{
    __shared__ float ts[32][33];
    const int n0 = blockIdx.x * 32;
    const int k0 = blockIdx.y * 32;
    const int tx = threadIdx.x;
    const int ty = threadIdx.y;
#pragma unroll
    for (int i = 0; i < 4; i++) {
        int k = k0 + ty + i * 8;
        ts[ty + i * 8][tx] = src[(size_t)k * N + n0 + tx];
    }
    __syncthreads();
#pragma unroll
    for (int i = 0; i < 4; i++) {
        int n = n0 + ty + i * 8;
        float v = ts[tx][ty + i * 8];
        __nv_bfloat16 h = __float2bfloat16(v);
        size_t idx = (size_t)n * K + k0 + tx;
        hi[idx] = h;
        lo[idx] = __float2bfloat16(v - __bfloat162float(h));
    }
}

// ================= persistent bf16 split-2 tensor-core GEMM =================
// C = A[M,K] @ W[K,N] + bias; A = (Ahi+Alo) bf16 [M][K], W = (Bhi+Blo) [N][K].
// D += Ahi*Bhi + Ahi*Blo + Alo*Bhi. Persistent CTAs + atomic tile stealing.
#define GBM 128
#define GBN 128
#define GBK 32
#define TSTRIDE 20                     // uint32 words per SMEM tile row (80 B)
#define TILE_WORDS (128 * TSTRIDE)
#define GEMM_GRID 304                  // 2 CTAs x 152 SMs

__global__ __launch_bounds__(256, 2) void gemm_bf16x2_kernel(
    const __nv_bfloat16* __restrict__ Ahi, const __nv_bfloat16* __restrict__ Alo,
    const __nv_bfloat16* __restrict__ Bhi, const __nv_bfloat16* __restrict__ Blo,
    const float* __restrict__ bias,
    float* __restrict__ Cout,                     // fp32 path (if Chi==nullptr)
    __nv_bfloat16* __restrict__ Chi,              // hi/lo path
    __nv_bfloat16* __restrict__ Clo,
    int M, int N, int K, int ctr_slot)
{
    extern __shared__ uint32_t sm[];
    __shared__ int s_next;
    uint32_t* tiles[2][4];   // 0=Ahi 1=Alo 2=Bhi 3=Blo
#pragma unroll
    for (int b = 0; b < 2; b++)
#pragma unroll
        for (int t = 0; t < 4; t++)
            tiles[b][t] = sm + (b * 4 + t) * TILE_WORDS;

    const int tid  = threadIdx.x;
    const int wid  = tid >> 5;
    const int lane = tid & 31;
    const int g    = lane >> 2;
    const int q    = lane & 3;
    const int wm   = (wid & 1) * 64;
    const int wn   = (wid >> 1) * 32;

    const int grp = lane >> 3;
    const int rl  = lane & 7;
    uint32_t aRel[4];
#pragma unroll
    for (int mi = 0; mi < 4; mi++)
        aRel[mi] = (uint32_t)((wm + mi * 16 + (grp & 1) * 8 + rl) * 80
                              + (grp >> 1) * 16);
    uint32_t bRel[2];
#pragma unroll
    for (int ni2 = 0; ni2 < 2; ni2++)
        bRel[ni2] = (uint32_t)((wn + ni2 * 16 + (grp >> 1) * 8 + rl) * 80
                               + (grp & 1) * 16);

    const int ncol    = N / GBN;
    const int n_tiles = (M / GBM) * ncol;
    int ti = blockIdx.x;                       // implicit first tile

    while (ti < n_tiles) {
        const int row0 = (ti / ncol) * GBM;
        const int col0 = (ti % ncol) * GBN;

        float acc[4][4][4];
#pragma unroll
        for (int mi = 0; mi < 4; mi++)
#pragma unroll
            for (int ni = 0; ni < 4; ni++)
#pragma unroll
                for (int r = 0; r < 4; r++) acc[mi][ni][r] = 0.f;

        const __nv_bfloat16* srcs[4] = {Ahi, Alo, Bhi, Blo};
        auto load_tile = [&](int kt, int buf) {
            const int k0 = kt * GBK;
#pragma unroll
            for (int t = 0; t < 4; t++) {
                const __nv_bfloat16* base = srcs[t] +
                    (size_t)((t < 2) ? row0 : col0) * K + k0;
#pragma unroll
                for (int it = 0; it < 2; it++) {
                    int idx = tid + it * 256;
                    int r   = idx >> 2;
                    int f   = idx & 3;
                    cp_async16(&tiles[buf][t][r * TSTRIDE + f * 4],
                               base + (size_t)r * K + f * 8);
                }
            }
            cp_commit();
        };

        load_tile(0, 0);
        cp_wait0();
        __syncthreads();

        const int KT = K / GBK;
        for (int kt = 0; kt < KT; kt++) {
            const int buf = kt & 1;
            if (kt + 1 < KT) load_tile(kt + 1, buf ^ 1);

            const uint32_t baseAh = smem_u32(tiles[buf][0]);
            const uint32_t baseAl = smem_u32(tiles[buf][1]);
            const uint32_t baseBh = smem_u32(tiles[buf][2]);
            const uint32_t baseBl = smem_u32(tiles[buf][3]);

#pragma unroll
            for (int ks = 0; ks < 2; ks++) {
                const uint32_t ko = (uint32_t)ks * 32;
                uint32_t ah[4][4], al[4][4], bh[4][2], bl[4][2];
#pragma unroll
                for (int mi = 0; mi < 4; mi++) {
                    ldsm_x4(ah[mi], baseAh + aRel[mi] + ko);
                    ldsm_x4(al[mi], baseAl + aRel[mi] + ko);
                }
#pragma unroll
                for (int ni2 = 0; ni2 < 2; ni2++) {
                    uint32_t t4[4];
                    ldsm_x4(t4, baseBh + bRel[ni2] + ko);
                    bh[2*ni2][0] = t4[0]; bh[2*ni2][1] = t4[1];
                    bh[2*ni2+1][0] = t4[2]; bh[2*ni2+1][1] = t4[3];
                    ldsm_x4(t4, baseBl + bRel[ni2] + ko);
                    bl[2*ni2][0] = t4[0]; bl[2*ni2][1] = t4[1];
                    bl[2*ni2+1][0] = t4[2]; bl[2*ni2+1][1] = t4[3];
                }
                // term-major ordering: 16 independent accumulators between
                // reuses of any D register (breaks HMMA RAW chains)
#pragma unroll
                for (int mi = 0; mi < 4; mi++)
#pragma unroll
                    for (int ni = 0; ni < 4; ni++)
                        mma_bf16(acc[mi][ni], ah[mi], bh[ni]);
#pragma unroll
                for (int mi = 0; mi < 4; mi++)
#pragma unroll
                    for (int ni = 0; ni < 4; ni++)
                        mma_bf16(acc[mi][ni], ah[mi], bl[ni]);
#pragma unroll
                for (int mi = 0; mi < 4; mi++)
#pragma unroll
                    for (int ni = 0; ni < 4; ni++)
                        mma_bf16(acc[mi][ni], al[mi], bh[ni]);
            }

            if (kt + 1 < KT) cp_wait0();
            __syncthreads();
        }

        // ---- epilogue ----
#pragma unroll
        for (int mi = 0; mi < 4; mi++) {
#pragma unroll
            for (int ni = 0; ni < 4; ni++) {
                int r = row0 + wm + mi * 16 + g;
                int c = col0 + wn + ni * 8 + 2 * q;
                float b0 = bias[c], b1 = bias[c + 1];
                float v00 = acc[mi][ni][0] + b0, v01 = acc[mi][ni][1] + b1;
                float v10 = acc[mi][ni][2] + b0, v11 = acc[mi][ni][3] + b1;
                if (Chi) {
                    float r0, r1;
                    uint32_t hw0 = pack_hi_pair(v00, v01, r0, r1);
                    uint32_t lw0 = pack_bf16x2(r0, r1);
                    uint32_t hw1 = pack_hi_pair(v10, v11, r0, r1);
                    uint32_t lw1 = pack_bf16x2(r0, r1);
                    *(uint32_t*)(Chi + (size_t)r * N + c)       = hw0;
                    *(uint32_t*)(Clo + (size_t)r * N + c)       = lw0;
                    *(uint32_t*)(Chi + (size_t)(r + 8) * N + c) = hw1;
                    *(uint32_t*)(Clo + (size_t)(r + 8) * N + c) = lw1;
                } else {
                    *(float2*)(Cout + (size_t)r * N + c)       = make_float2(v00, v01);
                    *(float2*)(Cout + (size_t)(r + 8) * N + c) = make_float2(v10, v11);
                }
            }
        }

        // ---- grab next tile (work stealing) ----
        if (tid == 0) s_next = (int)gridDim.x + atomicAdd(&g_ctr[ctr_slot], 1);
        __syncthreads();
        ti = s_next;
        __syncthreads();   // keep s_next stable before next iteration's reuse
    }
}

// ================= MMA flash attention (bf16 hi/lo inputs, fp32 softmax) ========
// Block: 256 threads = 8 warps, 128 queries of one (b,h). 64-key tiles,
// double-buffered cp.async. K via ldmatrix, V via ldmatrix.trans.
// SMEM buffer (uint32 words, per buf 9216 = 36 KB): Khi@0 Klo@2304 Vhi@4608 Vlo@6912
// rows: 64 bf16 = 128 B + 16 B pad => 36 words/row (conflict-free ldmatrix).
#define ATT_SMEM (2 * 9216 * 4)

__global__ __launch_bounds__(256) void attn_mma_kernel(
    const __nv_bfloat16* __restrict__ qkvhi,
    const __nv_bfloat16* __restrict__ qkvlo,
    __nv_bfloat16* __restrict__ yhi, __nv_bfloat16* __restrict__ ylo)
{
    extern __shared__ uint32_t smd[];
    uint32_t* smB[2] = {smd, smd + 9216};

    const int tid  = threadIdx.x;
    const int w    = tid >> 5;
    const int lane = tid & 31;
    const int g    = lane >> 2;
    const int q    = lane & 3;
    const int grp  = lane >> 3;
    const int rl   = lane & 7;
    const int bh   = blockIdx.x;
    const int b    = bh >> 4;
    const int h    = bh & 15;
    const int qt   = (gridDim.y - 1) - blockIdx.y;   // heavy blocks first
    const int qb   = qt * 128;

    // ---- stage Q hi/lo into buffer 0, extract fragments, scale by 0.125 ----
#pragma unroll
    for (int it = 0; it < 8; it++) {
        int idx = tid + it * 256;            // 0..2047
        int arr = idx >> 10;                 // 0=hi,1=lo
        int rem = idx & 1023;
        int row = rem >> 3;
        int ch  = rem & 7;
        const __nv_bfloat16* src = (arr ? qkvlo : qkvhi)
            + (size_t)(b * T_ + qb + row) * C3_ + h * HD_ + ch * 8;
        cp_async16(&smB[0][arr * 4608 + row * 36 + ch * 4], src);
    }
    cp_commit();
    cp_wait0();
    __syncthreads();

    uint32_t qh[4][4], ql[4][4];
    {
        uint32_t qa = smem_u32(&smB[0][0])
            + (uint32_t)((w * 16 + (grp & 1) * 8 + rl) * 144 + (grp >> 1) * 16);
#pragma unroll
        for (int ks = 0; ks < 4; ks++) {
            ldsm_x4(qh[ks], qa + ks * 32);
            ldsm_x4(ql[ks], qa + 4608 * 4 + ks * 32);
        }
        const __nv_bfloat162 sc = __float2bfloat162_rn(0.125f);  // exact scale
#pragma unroll
        for (int ks = 0; ks < 4; ks++)
#pragma unroll
            for (int i = 0; i < 4; i++) {
                __nv_bfloat162 t = *(__nv_bfloat162*)&qh[ks][i];
                t = __hmul2(t, sc);
                qh[ks][i] = *(uint32_t*)&t;
                t = *(__nv_bfloat162*)&ql[ks][i];
                t = __hmul2(t, sc);
                ql[ks][i] = *(uint32_t*)&t;
            }
    }
    __syncthreads();   // buffer 0 free for K/V

    // K/V tile sources: [arr] 0=Khi 1=Klo 2=Vhi 3=Vlo
    const __nv_bfloat16* kv_src[4] = {
        qkvhi + C_, qkvlo + C_, qkvhi + 2 * C_, qkvlo + 2 * C_
    };
    auto load_tile = [&](int kt, int bufi) {
        const int k0 = kt * 64;
#pragma unroll
        for (int it = 0; it < 8; it++) {
            int idx = tid + it * 256;        // 0..2047
            int arr = idx >> 9;              // 0..3
            int rem = idx & 511;
            int row = rem >> 3;
            int ch  = rem & 7;
            const __nv_bfloat16* src = kv_src[arr]
                + (size_t)(b * T_ + k0 + row) * C3_ + h * HD_ + ch * 8;
            cp_async16(&smB[bufi][arr * 2304 + row * 36 + ch * 4], src);
        }
        cp_commit();
    };

    float o[8][4];
#pragma unroll
    for (int nj = 0; nj < 8; nj++)
#pragma unroll
        for (int c = 0; c < 4; c++) o[nj][c] = 0.f;
    float m0 = -INFINITY, m1 = -INFINITY;
    float l0 = 0.f, l1 = 0.f;

    const int qrow0 = qb + w * 16 + g;
    const int qrow1 = qrow0 + 8;
    const int qmax_w = qb + w * 16 + 15;
    const int kt_max = (qb + 127) >> 6;

    load_tile(0, 0);
    cp_wait0();
    __syncthreads();

    for (int kt = 0; kt <= kt_max; kt++) {
        const int bufi = kt & 1;
        const int k0 = kt * 64;
        if (kt + 1 <= kt_max) load_tile(kt + 1, bufi ^ 1);

        if (k0 <= qmax_w) {
            const uint32_t sb = smem_u32(&smB[bufi][0]);

            // ---- S = Q K^T (3-term split) ----
            float s[8][4];
#pragma unroll
            for (int ni2 = 0; ni2 < 4; ni2++) {
#pragma unroll
                for (int c = 0; c < 4; c++) {
                    s[2*ni2][c] = 0.f; s[2*ni2+1][c] = 0.f;
                }
                const uint32_t ka = sb
                    + (uint32_t)((ni2 * 16 + (grp >> 1) * 8 + rl) * 144
                                 + (grp & 1) * 16);
#pragma unroll
                for (int ks = 0; ks < 4; ks++) {
                    uint32_t bh4[4], bl4[4];
                    ldsm_x4(bh4, ka + ks * 32);
                    ldsm_x4(bl4, ka + 2304 * 4 + ks * 32);
                    mma_bf16(s[2*ni2],   qh[ks], bh4);
                    mma_bf16(s[2*ni2],   qh[ks], bl4);
                    mma_bf16(s[2*ni2],   ql[ks], bh4);
                    mma_bf16(s[2*ni2+1], qh[ks], bh4 + 2);
                    mma_bf16(s[2*ni2+1], qh[ks], bl4 + 2);
                    mma_bf16(s[2*ni2+1], ql[ks], bh4 + 2);
                }
            }

            // ---- causal mask ----
            if (k0 + 63 > qb + w * 16) {
#pragma unroll
                for (int ni = 0; ni < 8; ni++) {
                    int key = k0 + 8 * ni + 2 * q;
                    s[ni][0] = (key     <= qrow0) ? s[ni][0] : -INFINITY;
                    s[ni][1] = (key + 1 <= qrow0) ? s[ni][1] : -INFINITY;
                    s[ni][2] = (key     <= qrow1) ? s[ni][2] : -INFINITY;
                    s[ni][3] = (key + 1 <= qrow1) ? s[ni][3] : -INFINITY;
                }
            }

            // ---- online softmax ----
            float mx0 = s[0][0], mx1 = s[0][2];
#pragma unroll
            for (int ni = 0; ni < 8; ni++) {
                mx0 = fmaxf(mx0, fmaxf(s[ni][0], s[ni][1]));
                mx1 = fmaxf(mx1, fmaxf(s[ni][2], s[ni][3]));
            }
            mx0 = fmaxf(mx0, __shfl_xor_sync(0xffffffff, mx0, 1));
            mx0 = fmaxf(mx0, __shfl_xor_sync(0xffffffff, mx0, 2));
            mx1 = fmaxf(mx1, __shfl_xor_sync(0xffffffff, mx1, 1));
            mx1 = fmaxf(mx1, __shfl_xor_sync(0xffffffff, mx1, 2));

            float mn0 = fmaxf(m0, mx0), mn1 = fmaxf(m1, mx1);
            float al0 = __expf(m0 - mn0), al1 = __expf(m1 - mn1);
            m0 = mn0; m1 = mn1;
            l0 *= al0; l1 *= al1;
#pragma unroll
            for (int nj = 0; nj < 8; nj++) {
                o[nj][0] *= al0; o[nj][1] *= al0;
                o[nj][2] *= al1; o[nj][3] *= al1;
            }

            // ---- per k16 step: pack P, accumulate O += P V ----
#pragma unroll
            for (int ks = 0; ks < 4; ks++) {
                uint32_t af_hi[4], af_lo[4];
#pragma unroll
                for (int half = 0; half < 2; half++) {
                    const int ni = 2 * ks + half;
                    float p0 = __expf(s[ni][0] - mn0);
                    float p1 = __expf(s[ni][1] - mn0);
                    float p2 = __expf(s[ni][2] - mn1);
                    float p3 = __expf(s[ni][3] - mn1);
                    l0 += p0 + p1;
                    l1 += p2 + p3;
                    float r0, r1, r2, r3;
                    af_hi[2*half]     = pack_hi_pair(p0, p1, r0, r1);
                    af_lo[2*half]     = pack_bf16x2(r0, r1);
                    af_hi[2*half + 1] = pack_hi_pair(p2, p3, r2, r3);
                    af_lo[2*half + 1] = pack_bf16x2(r2, r3);
                }
                const uint32_t va = sb + 4608 * 4
                    + (uint32_t)((ks * 16 + (grp & 1) * 8 + rl) * 144
                                 + (grp >> 1) * 16);
#pragma unroll
                for (int nj2 = 0; nj2 < 4; nj2++) {
                    uint32_t vh4[4], vl4[4];
                    ldsm_x4_trans(vh4, va + nj2 * 32);
                    ldsm_x4_trans(vl4, va + 2304 * 4 + nj2 * 32);
                    mma_bf16(o[2*nj2],   af_hi, vh4);
                    mma_bf16(o[2*nj2],   af_hi, vl4);
                    mma_bf16(o[2*nj2],   af_lo, vh4);
                    mma_bf16(o[2*nj2+1], af_hi, vh4 + 2);
                    mma_bf16(o[2*nj2+1], af_hi, vl4 + 2);
                    mma_bf16(o[2*nj2+1], af_lo, vh4 + 2);
                }
            }
        }

        cp_wait0();
        __syncthreads();
    }

    // ---- epilogue ----
    l0 += __shfl_xor_sync(0xffffffff, l0, 1);
    l0 += __shfl_xor_sync(0xffffffff, l0, 2);
    l1 += __shfl_xor_sync(0xffffffff, l1, 1);
    l1 += __shfl_xor_sync(0xffffffff, l1, 2);
    const float inv0 = 1.f / l0;
    const float inv1 = 1.f / l1;

    __nv_bfloat16* yh0 = yhi + (size_t)(b * T_ + qrow0) * C_ + h * HD_;
    __nv_bfloat16* yl0 = ylo + (size_t)(b * T_ + qrow0) * C_ + h * HD_;
    __nv_bfloat16* yh1 = yhi + (size_t)(b * T_ + qrow1) * C_ + h * HD_;
    __nv_bfloat16* yl1 = ylo + (size_t)(b * T_ + qrow1) * C_ + h * HD_;
#pragma unroll
    for (int nj = 0; nj < 8; nj++) {
        int c = 8 * nj + 2 * q;
        float a0 = o[nj][0] * inv0, a1 = o[nj][1] * inv0;
        float a2 = o[nj][2] * inv1, a3 = o[nj][3] * inv1;
        float r0, r1, r2, r3;
        uint32_t h01 = pack_hi_pair(a0, a1, r0, r1);
        uint32_t h23 = pack_hi_pair(a2, a3, r2, r3);
        *(uint32_t*)(yh0 + c) = h01;
        *(uint32_t*)(yl0 + c) = pack_bf16x2(r0, r1);
        *(uint32_t*)(yh1 + c) = h23;
        *(uint32_t*)(yl1 + c) = pack_bf16x2(r2, r3);
    }
}

// ---------------- launch ----------------
extern "C" void kernel_launch(void* const* d_in, const int* in_sizes, int n_in,
                              void* d_out, int out_size)
{
    const float* x     = (const float*)d_in[0];
    const float* w_qkv = (const float*)d_in[1];
    const float* b_qkv = (const float*)d_in[2];
    const float* w_out = (const float*)d_in[3];
    const float* b_out = (const float*)d_in[4];
    float* out = (float*)d_out;

    __nv_bfloat16 *qkvhi, *qkvlo, *xhi, *xlo, *yhi, *ylo, *wqhi, *wqlo, *wohi, *wolo;
    cudaGetSymbolAddress((void**)&qkvhi, g_qkv_hi);
    cudaGetSymbolAddress((void**)&qkvlo, g_qkv_lo);
    cudaGetSymbolAddress((void**)&xhi, g_x_hi);
    cudaGetSymbolAddress((void**)&xlo, g_x_lo);
    cudaGetSymbolAddress((void**)&yhi, g_y_hi);
    cudaGetSymbolAddress((void**)&ylo, g_y_lo);
    cudaGetSymbolAddress((void**)&wqhi, g_wqkvT_hi);
    cudaGetSymbolAddress((void**)&wqlo, g_wqkvT_lo);
    cudaGetSymbolAddress((void**)&wohi, g_woutT_hi);
    cudaGetSymbolAddress((void**)&wolo, g_woutT_lo);

    static bool attr_set = false;
    if (!attr_set) {
        cudaFuncSetAttribute(gemm_bf16x2_kernel,
                             cudaFuncAttributeMaxDynamicSharedMemorySize,
                             8 * TILE_WORDS * 4);
        cudaFuncSetAttribute(attn_mma_kernel,
                             cudaFuncAttributeMaxDynamicSharedMemorySize,
                             ATT_SMEM);
        attr_set = true;
    }
    const int gemm_smem = 8 * TILE_WORDS * 4;   // 81920 B

    split_f32_kernel<<<1024, 256>>>(x, xhi, xlo, M_ * C_);   // also resets g_ctr
    {
        dim3 grid(C3_ / 32, C_ / 32), blk(32, 8);
        split_transpose_kernel<<<grid, blk>>>(w_qkv, wqhi, wqlo, C_, C3_);
    }
    {
        dim3 grid(C_ / 32, C_ / 32), blk(32, 8);
        split_transpose_kernel<<<grid, blk>>>(w_out, wohi, wolo, C_, C_);
    }

    // 1) qkv = x @ w_qkv + b_qkv  -> hi/lo bf16  (persistent, ctr 0)
    gemm_bf16x2_kernel<<<GEMM_GRID, 256, gemm_smem>>>(
        xhi, xlo, wqhi, wqlo, b_qkv, nullptr, qkvhi, qkvlo, M_, C3_, C_, 0);

    // 2) causal attention -> y (hi/lo bf16)
    {
        dim3 grid(B_ * H_, T_ / 128);
        attn_mma_kernel<<<grid, 256, ATT_SMEM>>>(qkvhi, qkvlo, yhi, ylo);
    }

    // 3) out = y @ w_out + b_out  -> fp32  (persistent, ctr 1)
    gemm_bf16x2_kernel<<<GEMM_GRID, 256, gemm_smem>>>(
        yhi, ylo, wohi, wolo, b_out, out, nullptr, nullptr, M_, C_, C_, 1);
}

// round 9
// speedup vs baseline: 1.0152x; 1.0152x over previous
#include <cuda_runtime.h>
#include <cuda_bf16.h>
#include <math.h>
#include <stdint.h>

// Problem dims (fixed by the dataset)
#define B_   2
#define T_   2048
#define C_   1024
#define H_   16
#define HD_  64
#define C3_  (3*C_)
#define M_   (B_*T_)          // 4096 rows

// ---------------- scratch (no cudaMalloc allowed) ----------------
__device__ __nv_bfloat16 g_qkv_hi[(size_t)M_ * C3_];
__device__ __nv_bfloat16 g_qkv_lo[(size_t)M_ * C3_];
__device__ __nv_bfloat16 g_x_hi[(size_t)M_ * C_];
__device__ __nv_bfloat16 g_x_lo[(size_t)M_ * C_];
__device__ __nv_bfloat16 g_y_hi[(size_t)M_ * C_];
__device__ __nv_bfloat16 g_y_lo[(size_t)M_ * C_];
__device__ __nv_bfloat16 g_wqkvT_hi[(size_t)C3_ * C_];  // [N=3C][K=C]
__device__ __nv_bfloat16 g_wqkvT_lo[(size_t)C3_ * C_];
__device__ __nv_bfloat16 g_woutT_hi[(size_t)C_ * C_];   // [N=C][K=C]
__device__ __nv_bfloat16 g_woutT_lo[(size_t)C_ * C_];
__device__ int g_ctr[2];                                // persistent-GEMM tile counters

// ---------------- helpers ----------------
__device__ __forceinline__ uint32_t smem_u32(const void* p) {
    return (uint32_t)__cvta_generic_to_shared(p);
}
__device__ __forceinline__ void cp_async16(void* s, const void* g) {
    asm volatile("cp.async.cg.shared.global [%0], [%1], 16;\n"
                 :: "r"(smem_u32(s)), "l"(g));
}
__device__ __forceinline__ void cp_commit() {
    asm volatile("cp.async.commit_group;\n" ::);
}
__device__ __forceinline__ void cp_wait0() {
    asm volatile("cp.async.wait_group 0;\n" ::);
}
__device__ __forceinline__ void mma_bf16(float* d, const uint32_t* a, const uint32_t* b) {
    asm volatile(
        "mma.sync.aligned.m16n8k16.row.col.f32.bf16.bf16.f32 "
        "{%0,%1,%2,%3}, {%4,%5,%6,%7}, {%8,%9}, {%0,%1,%2,%3};\n"
        : "+f"(d[0]), "+f"(d[1]), "+f"(d[2]), "+f"(d[3])
        : "r"(a[0]), "r"(a[1]), "r"(a[2]), "r"(a[3]),
          "r"(b[0]), "r"(b[1]));
}
__device__ __forceinline__ void ldsm_x4(uint32_t* r, uint32_t addr) {
    asm volatile("ldmatrix.sync.aligned.m8n8.x4.shared.b16 {%0,%1,%2,%3}, [%4];"
                 : "=r"(r[0]), "=r"(r[1]), "=r"(r[2]), "=r"(r[3])
                 : "r"(addr));
}
__device__ __forceinline__ void ldsm_x4_trans(uint32_t* r, uint32_t addr) {
    asm volatile("ldmatrix.sync.aligned.m8n8.x4.trans.shared.b16 {%0,%1,%2,%3}, [%4];"
                 : "=r"(r[0]), "=r"(r[1]), "=r"(r[2]), "=r"(r[3])
                 : "r"(addr));
}
__device__ __forceinline__ uint32_t pack_bf16x2(float lo, float hi) {
    uint32_t r;
    asm("cvt.rn.bf16x2.f32 %0, %1, %2;" : "=r"(r) : "f"(hi), "f"(lo));
    return r;
}
__device__ __forceinline__ uint32_t pack_hi_pair(float a, float b,
                                                 float& ra, float& rb) {
    uint32_t w = pack_bf16x2(a, b);
    __nv_bfloat162 h = *reinterpret_cast<__nv_bfloat162*>(&w);
    ra = a - __bfloat162float(h.x);
    rb = b - __bfloat162float(h.y);
    return w;
}

// ---------------- prep kernels ----------------
__global__ void split_f32_kernel(const float* __restrict__ src,
                                 __nv_bfloat16* __restrict__ hi,
                                 __nv_bfloat16* __restrict__ lo, int n)
{
    if (blockIdx.x == 0 && threadIdx.x == 0) {   // reset persistent-GEMM counters
        g_ctr[0] = 0;
        g_ctr[1] = 0;
    }
    int i = blockIdx.x * blockDim.x + threadIdx.x;
    int stride = gridDim.x * blockDim.x;
    for (; i < n; i += stride) {
        float v = src[i];
        __nv_bfloat16 h = __float2bfloat16(v);
        hi[i] = h;
        lo[i] = __float2bfloat16(v - __bfloat162float(h));
    }
}

__global__ void split_transpose_kernel(const float* __restrict__ src,
                                       __nv_bfloat16* __restrict__ hi,
                                       __nv_bfloat16* __restrict__ lo,
                                       int K, int N)
{
    __shared__ float ts[32][33];
    const int n0 = blockIdx.x * 32;
    const int k0 = blockIdx.y * 32;
    const int tx = threadIdx.x;
    const int ty = threadIdx.y;
#pragma unroll
    for (int i = 0; i < 4; i++) {
        int k = k0 + ty + i * 8;
        ts[ty + i * 8][tx] = src[(size_t)k * N + n0 + tx];
    }
    __syncthreads();
#pragma unroll
    for (int i = 0; i < 4; i++) {
        int n = n0 + ty + i * 8;
        float v = ts[tx][ty + i * 8];
        __nv_bfloat16 h = __float2bfloat16(v);
        size_t idx = (size_t)n * K + k0 + tx;
        hi[idx] = h;
        lo[idx] = __float2bfloat16(v - __bfloat162float(h));
    }
}

// ================= persistent bf16 split-2 tensor-core GEMM =================
// C = A[M,K] @ W[K,N] + bias; A = (Ahi+Alo) bf16 [M][K], W = (Bhi+Blo) [N][K].
// D += Ahi*Bhi + Ahi*Blo + Alo*Bhi. Persistent CTAs + atomic tile stealing.
// 128 threads = 4 warps (2x2), warp tile 64x64 (squares the FLOP/SMEM-byte
// ratio: 24 FLOP/B vs 16 at 64x32 -> crossbar no longer binds the tensor pipe).
#define GBM 128
#define GBN 128
#define GBK 32
#define TSTRIDE 20                     // uint32 words per SMEM tile row (80 B)
#define TILE_WORDS (128 * TSTRIDE)
#define GEMM_GRID 304                  // 2 CTAs x 152 SMs

__global__ __launch_bounds__(128, 2) void gemm_bf16x2_kernel(
    const __nv_bfloat16* __restrict__ Ahi, const __nv_bfloat16* __restrict__ Alo,
    const __nv_bfloat16* __restrict__ Bhi, const __nv_bfloat16* __restrict__ Blo,
    const float* __restrict__ bias,
    float* __restrict__ Cout,                     // fp32 path (if Chi==nullptr)
    __nv_bfloat16* __restrict__ Chi,              // hi/lo path
    __nv_bfloat16* __restrict__ Clo,
    int M, int N, int K, int ctr_slot)
{
    extern __shared__ uint32_t sm[];
    __shared__ int s_next;
    uint32_t* tiles[2][4];   // 0=Ahi 1=Alo 2=Bhi 3=Blo
#pragma unroll
    for (int b = 0; b < 2; b++)
#pragma unroll
        for (int t = 0; t < 4; t++)
            tiles[b][t] = sm + (b * 4 + t) * TILE_WORDS;

    const int tid  = threadIdx.x;
    const int wid  = tid >> 5;
    const int lane = tid & 31;
    const int g    = lane >> 2;
    const int q    = lane & 3;
    const int wm   = (wid & 1) * 64;
    const int wn   = (wid >> 1) * 64;

    const int grp = lane >> 3;
    const int rl  = lane & 7;
    uint32_t aRel[4];
#pragma unroll
    for (int mi = 0; mi < 4; mi++)
        aRel[mi] = (uint32_t)((wm + mi * 16 + (grp & 1) * 8 + rl) * 80
                              + (grp >> 1) * 16);
    uint32_t bRel[4];
#pragma unroll
    for (int ni2 = 0; ni2 < 4; ni2++)
        bRel[ni2] = (uint32_t)((wn + ni2 * 16 + (grp >> 1) * 8 + rl) * 80
                               + (grp & 1) * 16);

    const int ncol    = N / GBN;
    const int n_tiles = (M / GBM) * ncol;
    int ti = blockIdx.x;                       // implicit first tile

    while (ti < n_tiles) {
        const int row0 = (ti / ncol) * GBM;
        const int col0 = (ti % ncol) * GBN;

        float acc[4][8][4];
#pragma unroll
        for (int mi = 0; mi < 4; mi++)
#pragma unroll
            for (int ni = 0; ni < 8; ni++)
#pragma unroll
                for (int r = 0; r < 4; r++) acc[mi][ni][r] = 0.f;

        const __nv_bfloat16* srcs[4] = {Ahi, Alo, Bhi, Blo};
        auto load_tile = [&](int kt, int buf) {
            const int k0 = kt * GBK;
#pragma unroll
            for (int t = 0; t < 4; t++) {
                const __nv_bfloat16* base = srcs[t] +
                    (size_t)((t < 2) ? row0 : col0) * K + k0;
#pragma unroll
                for (int it = 0; it < 4; it++) {
                    int idx = tid + it * 128;       // 0..511
                    int r   = idx >> 2;
                    int f   = idx & 3;
                    cp_async16(&tiles[buf][t][r * TSTRIDE + f * 4],
                               base + (size_t)r * K + f * 8);
                }
            }
            cp_commit();
        };

        load_tile(0, 0);
        cp_wait0();
        __syncthreads();

        const int KT = K / GBK;
        for (int kt = 0; kt < KT; kt++) {
            const int buf = kt & 1;
            if (kt + 1 < KT) load_tile(kt + 1, buf ^ 1);

            const uint32_t baseAh = smem_u32(tiles[buf][0]);
            const uint32_t baseAl = smem_u32(tiles[buf][1]);
            const uint32_t baseBh = smem_u32(tiles[buf][2]);
            const uint32_t baseBl = smem_u32(tiles[buf][3]);

#pragma unroll
            for (int ks = 0; ks < 2; ks++) {
                const uint32_t ko = (uint32_t)ks * 32;
                uint32_t ah[4][4], al[4][4], bh[8][2], bl[8][2];
#pragma unroll
                for (int mi = 0; mi < 4; mi++) {
                    ldsm_x4(ah[mi], baseAh + aRel[mi] + ko);
                    ldsm_x4(al[mi], baseAl + aRel[mi] + ko);
                }
#pragma unroll
                for (int ni2 = 0; ni2 < 4; ni2++) {
                    uint32_t t4[4];
                    ldsm_x4(t4, baseBh + bRel[ni2] + ko);
                    bh[2*ni2][0] = t4[0]; bh[2*ni2][1] = t4[1];
                    bh[2*ni2+1][0] = t4[2]; bh[2*ni2+1][1] = t4[3];
                    ldsm_x4(t4, baseBl + bRel[ni2] + ko);
                    bl[2*ni2][0] = t4[0]; bl[2*ni2][1] = t4[1];
                    bl[2*ni2+1][0] = t4[2]; bl[2*ni2+1][1] = t4[3];
                }
#pragma unroll
                for (int mi = 0; mi < 4; mi++)
#pragma unroll
                    for (int ni = 0; ni < 8; ni++)
                        mma_bf16(acc[mi][ni], ah[mi], bh[ni]);
#pragma unroll
                for (int mi = 0; mi < 4; mi++)
#pragma unroll
                    for (int ni = 0; ni < 8; ni++)
                        mma_bf16(acc[mi][ni], ah[mi], bl[ni]);
#pragma unroll
                for (int mi = 0; mi < 4; mi++)
#pragma unroll
                    for (int ni = 0; ni < 8; ni++)
                        mma_bf16(acc[mi][ni], al[mi], bh[ni]);
            }

            if (kt + 1 < KT) cp_wait0();
            __syncthreads();
        }

        // ---- epilogue ----
#pragma unroll
        for (int mi = 0; mi < 4; mi++) {
#pragma unroll
            for (int ni = 0; ni < 8; ni++) {
                int r = row0 + wm + mi * 16 + g;
                int c = col0 + wn + ni * 8 + 2 * q;
                float b0 = bias[c], b1 = bias[c + 1];
                float v00 = acc[mi][ni][0] + b0, v01 = acc[mi][ni][1] + b1;
                float v10 = acc[mi][ni][2] + b0, v11 = acc[mi][ni][3] + b1;
                if (Chi) {
                    float r0, r1;
                    uint32_t hw0 = pack_hi_pair(v00, v01, r0, r1);
                    uint32_t lw0 = pack_bf16x2(r0, r1);
                    uint32_t hw1 = pack_hi_pair(v10, v11, r0, r1);
                    uint32_t lw1 = pack_bf16x2(r0, r1);
                    *(uint32_t*)(Chi + (size_t)r * N + c)       = hw0;
                    *(uint32_t*)(Clo + (size_t)r * N + c)       = lw0;
                    *(uint32_t*)(Chi + (size_t)(r + 8) * N + c) = hw1;
                    *(uint32_t*)(Clo + (size_t)(r + 8) * N + c) = lw1;
                } else {
                    *(float2*)(Cout + (size_t)r * N + c)       = make_float2(v00, v01);
                    *(float2*)(Cout + (size_t)(r + 8) * N + c) = make_float2(v10, v11);
                }
            }
        }

        // ---- grab next tile (work stealing) ----
        if (tid == 0) s_next = (int)gridDim.x + atomicAdd(&g_ctr[ctr_slot], 1);
        __syncthreads();
        ti = s_next;
        __syncthreads();   // keep s_next stable before next iteration's reuse
    }
}

// ================= MMA flash attention (bf16 hi/lo inputs, fp32 softmax) ========
// Block: 256 threads = 8 warps, 128 queries of one (b,h). 64-key tiles,
// double-buffered cp.async. K via ldmatrix, V via ldmatrix.trans.
// SMEM buffer (uint32 words, per buf 9216 = 36 KB): Khi@0 Klo@2304 Vhi@4608 Vlo@6912
// rows: 64 bf16 = 128 B + 16 B pad => 36 words/row (conflict-free ldmatrix).
#define ATT_SMEM (2 * 9216 * 4)

__global__ __launch_bounds__(256) void attn_mma_kernel(
    const __nv_bfloat16* __restrict__ qkvhi,
    const __nv_bfloat16* __restrict__ qkvlo,
    __nv_bfloat16* __restrict__ yhi, __nv_bfloat16* __restrict__ ylo)
{
    extern __shared__ uint32_t smd[];
    uint32_t* smB[2] = {smd, smd + 9216};

    const int tid  = threadIdx.x;
    const int w    = tid >> 5;
    const int lane = tid & 31;
    const int g    = lane >> 2;
    const int q    = lane & 3;
    const int grp  = lane >> 3;
    const int rl   = lane & 7;
    const int bh   = blockIdx.x;
    const int b    = bh >> 4;
    const int h    = bh & 15;
    const int qt   = (gridDim.y - 1) - blockIdx.y;   // heavy blocks first
    const int qb   = qt * 128;

    // ---- stage Q hi/lo into buffer 0, extract fragments, scale by 0.125 ----
#pragma unroll
    for (int it = 0; it < 8; it++) {
        int idx = tid + it * 256;            // 0..2047
        int arr = idx >> 10;                 // 0=hi,1=lo
        int rem = idx & 1023;
        int row = rem >> 3;
        int ch  = rem & 7;
        const __nv_bfloat16* src = (arr ? qkvlo : qkvhi)
            + (size_t)(b * T_ + qb + row) * C3_ + h * HD_ + ch * 8;
        cp_async16(&smB[0][arr * 4608 + row * 36 + ch * 4], src);
    }
    cp_commit();
    cp_wait0();
    __syncthreads();

    uint32_t qh[4][4], ql[4][4];
    {
        uint32_t qa = smem_u32(&smB[0][0])
            + (uint32_t)((w * 16 + (grp & 1) * 8 + rl) * 144 + (grp >> 1) * 16);
#pragma unroll
        for (int ks = 0; ks < 4; ks++) {
            ldsm_x4(qh[ks], qa + ks * 32);
            ldsm_x4(ql[ks], qa + 4608 * 4 + ks * 32);
        }
        const __nv_bfloat162 sc = __float2bfloat162_rn(0.125f);  // exact scale
#pragma unroll
        for (int ks = 0; ks < 4; ks++)
#pragma unroll
            for (int i = 0; i < 4; i++) {
                __nv_bfloat162 t = *(__nv_bfloat162*)&qh[ks][i];
                t = __hmul2(t, sc);
                qh[ks][i] = *(uint32_t*)&t;
                t = *(__nv_bfloat162*)&ql[ks][i];
                t = __hmul2(t, sc);
                ql[ks][i] = *(uint32_t*)&t;
            }
    }
    __syncthreads();   // buffer 0 free for K/V

    // K/V tile sources: [arr] 0=Khi 1=Klo 2=Vhi 3=Vlo
    const __nv_bfloat16* kv_src[4] = {
        qkvhi + C_, qkvlo + C_, qkvhi + 2 * C_, qkvlo + 2 * C_
    };
    auto load_tile = [&](int kt, int bufi) {
        const int k0 = kt * 64;
#pragma unroll
        for (int it = 0; it < 8; it++) {
            int idx = tid + it * 256;        // 0..2047
            int arr = idx >> 9;              // 0..3
            int rem = idx & 511;
            int row = rem >> 3;
            int ch  = rem & 7;
            const __nv_bfloat16* src = kv_src[arr]
                + (size_t)(b * T_ + k0 + row) * C3_ + h * HD_ + ch * 8;
            cp_async16(&smB[bufi][arr * 2304 + row * 36 + ch * 4], src);
        }
        cp_commit();
    };

    float o[8][4];
#pragma unroll
    for (int nj = 0; nj < 8; nj++)
#pragma unroll
        for (int c = 0; c < 4; c++) o[nj][c] = 0.f;
    float m0 = -INFINITY, m1 = -INFINITY;
    float l0 = 0.f, l1 = 0.f;

    const int qrow0 = qb + w * 16 + g;
    const int qrow1 = qrow0 + 8;
    const int qmax_w = qb + w * 16 + 15;
    const int kt_max = (qb + 127) >> 6;

    load_tile(0, 0);
    cp_wait0();
    __syncthreads();

    for (int kt = 0; kt <= kt_max; kt++) {
        const int bufi = kt & 1;
        const int k0 = kt * 64;
        if (kt + 1 <= kt_max) load_tile(kt + 1, bufi ^ 1);

        if (k0 <= qmax_w) {
            const uint32_t sb = smem_u32(&smB[bufi][0]);

            // ---- S = Q K^T (3-term split) ----
            float s[8][4];
#pragma unroll
            for (int ni2 = 0; ni2 < 4; ni2++) {
#pragma unroll
                for (int c = 0; c < 4; c++) {
                    s[2*ni2][c] = 0.f; s[2*ni2+1][c] = 0.f;
                }
                const uint32_t ka = sb
                    + (uint32_t)((ni2 * 16 + (grp >> 1) * 8 + rl) * 144
                                 + (grp & 1) * 16);
#pragma unroll
                for (int ks = 0; ks < 4; ks++) {
                    uint32_t bh4[4], bl4[4];
                    ldsm_x4(bh4, ka + ks * 32);
                    ldsm_x4(bl4, ka + 2304 * 4 + ks * 32);
                    mma_bf16(s[2*ni2],   qh[ks], bh4);
                    mma_bf16(s[2*ni2],   qh[ks], bl4);
                    mma_bf16(s[2*ni2],   ql[ks], bh4);
                    mma_bf16(s[2*ni2+1], qh[ks], bh4 + 2);
                    mma_bf16(s[2*ni2+1], qh[ks], bl4 + 2);
                    mma_bf16(s[2*ni2+1], ql[ks], bh4 + 2);
                }
            }

            // ---- causal mask ----
            if (k0 + 63 > qb + w * 16) {
#pragma unroll
                for (int ni = 0; ni < 8; ni++) {
                    int key = k0 + 8 * ni + 2 * q;
                    s[ni][0] = (key     <= qrow0) ? s[ni][0] : -INFINITY;
                    s[ni][1] = (key + 1 <= qrow0) ? s[ni][1] : -INFINITY;
                    s[ni][2] = (key     <= qrow1) ? s[ni][2] : -INFINITY;
                    s[ni][3] = (key + 1 <= qrow1) ? s[ni][3] : -INFINITY;
                }
            }

            // ---- online softmax ----
            float mx0 = s[0][0], mx1 = s[0][2];
#pragma unroll
            for (int ni = 0; ni < 8; ni++) {
                mx0 = fmaxf(mx0, fmaxf(s[ni][0], s[ni][1]));
                mx1 = fmaxf(mx1, fmaxf(s[ni][2], s[ni][3]));
            }
            mx0 = fmaxf(mx0, __shfl_xor_sync(0xffffffff, mx0, 1));
            mx0 = fmaxf(mx0, __shfl_xor_sync(0xffffffff, mx0, 2));
            mx1 = fmaxf(mx1, __shfl_xor_sync(0xffffffff, mx1, 1));
            mx1 = fmaxf(mx1, __shfl_xor_sync(0xffffffff, mx1, 2));

            float mn0 = fmaxf(m0, mx0), mn1 = fmaxf(m1, mx1);
            float al0 = __expf(m0 - mn0), al1 = __expf(m1 - mn1);
            m0 = mn0; m1 = mn1;
            l0 *= al0; l1 *= al1;
#pragma unroll
            for (int nj = 0; nj < 8; nj++) {
                o[nj][0] *= al0; o[nj][1] *= al0;
                o[nj][2] *= al1; o[nj][3] *= al1;
            }

            // ---- per k16 step: pack P, accumulate O += P V ----
#pragma unroll
            for (int ks = 0; ks < 4; ks++) {
                uint32_t af_hi[4], af_lo[4];
#pragma unroll
                for (int half = 0; half < 2; half++) {
                    const int ni = 2 * ks + half;
                    float p0 = __expf(s[ni][0] - mn0);
                    float p1 = __expf(s[ni][1] - mn0);
                    float p2 = __expf(s[ni][2] - mn1);
                    float p3 = __expf(s[ni][3] - mn1);
                    l0 += p0 + p1;
                    l1 += p2 + p3;
                    float r0, r1, r2, r3;
                    af_hi[2*half]     = pack_hi_pair(p0, p1, r0, r1);
                    af_lo[2*half]     = pack_bf16x2(r0, r1);
                    af_hi[2*half + 1] = pack_hi_pair(p2, p3, r2, r3);
                    af_lo[2*half + 1] = pack_bf16x2(r2, r3);
                }
                const uint32_t va = sb + 4608 * 4
                    + (uint32_t)((ks * 16 + (grp & 1) * 8 + rl) * 144
                                 + (grp >> 1) * 16);
#pragma unroll
                for (int nj2 = 0; nj2 < 4; nj2++) {
                    uint32_t vh4[4], vl4[4];
                    ldsm_x4_trans(vh4, va + nj2 * 32);
                    ldsm_x4_trans(vl4, va + 2304 * 4 + nj2 * 32);
                    mma_bf16(o[2*nj2],   af_hi, vh4);
                    mma_bf16(o[2*nj2],   af_hi, vl4);
                    mma_bf16(o[2*nj2],   af_lo, vh4);
                    mma_bf16(o[2*nj2+1], af_hi, vh4 + 2);
                    mma_bf16(o[2*nj2+1], af_hi, vl4 + 2);
                    mma_bf16(o[2*nj2+1], af_lo, vh4 + 2);
                }
            }
        }

        cp_wait0();
        __syncthreads();
    }

    // ---- epilogue ----
    l0 += __shfl_xor_sync(0xffffffff, l0, 1);
    l0 += __shfl_xor_sync(0xffffffff, l0, 2);
    l1 += __shfl_xor_sync(0xffffffff, l1, 1);
    l1 += __shfl_xor_sync(0xffffffff, l1, 2);
    const float inv0 = 1.f / l0;
    const float inv1 = 1.f / l1;

    __nv_bfloat16* yh0 = yhi + (size_t)(b * T_ + qrow0) * C_ + h * HD_;
    __nv_bfloat16* yl0 = ylo + (size_t)(b * T_ + qrow0) * C_ + h * HD_;
    __nv_bfloat16* yh1 = yhi + (size_t)(b * T_ + qrow1) * C_ + h * HD_;
    __nv_bfloat16* yl1 = ylo + (size_t)(b * T_ + qrow1) * C_ + h * HD_;
#pragma unroll
    for (int nj = 0; nj < 8; nj++) {
        int c = 8 * nj + 2 * q;
        float a0 = o[nj][0] * inv0, a1 = o[nj][1] * inv0;
        float a2 = o[nj][2] * inv1, a3 = o[nj][3] * inv1;
        float r0, r1, r2, r3;
        uint32_t h01 = pack_hi_pair(a0, a1, r0, r1);
        uint32_t h23 = pack_hi_pair(a2, a3, r2, r3);
        *(uint32_t*)(yh0 + c) = h01;
        *(uint32_t*)(yl0 + c) = pack_bf16x2(r0, r1);
        *(uint32_t*)(yh1 + c) = h23;
        *(uint32_t*)(yl1 + c) = pack_bf16x2(r2, r3);
    }
}

// ---------------- launch ----------------
extern "C" void kernel_launch(void* const* d_in, const int* in_sizes, int n_in,
                              void* d_out, int out_size)
{
    const float* x     = (const float*)d_in[0];
    const float* w_qkv = (const float*)d_in[1];
    const float* b_qkv = (const float*)d_in[2];
    const float* w_out = (const float*)d_in[3];
    const float* b_out = (const float*)d_in[4];
    float* out = (float*)d_out;

    __nv_bfloat16 *qkvhi, *qkvlo, *xhi, *xlo, *yhi, *ylo, *wqhi, *wqlo, *wohi, *wolo;
    cudaGetSymbolAddress((void**)&qkvhi, g_qkv_hi);
    cudaGetSymbolAddress((void**)&qkvlo, g_qkv_lo);
    cudaGetSymbolAddress((void**)&xhi, g_x_hi);
    cudaGetSymbolAddress((void**)&xlo, g_x_lo);
    cudaGetSymbolAddress((void**)&yhi, g_y_hi);
    cudaGetSymbolAddress((void**)&ylo, g_y_lo);
    cudaGetSymbolAddress((void**)&wqhi, g_wqkvT_hi);
    cudaGetSymbolAddress((void**)&wqlo, g_wqkvT_lo);
    cudaGetSymbolAddress((void**)&wohi, g_woutT_hi);
    cudaGetSymbolAddress((void**)&wolo, g_woutT_lo);

    static bool attr_set = false;
    if (!attr_set) {
        cudaFuncSetAttribute(gemm_bf16x2_kernel,
                             cudaFuncAttributeMaxDynamicSharedMemorySize,
                             8 * TILE_WORDS * 4);
        cudaFuncSetAttribute(attn_mma_kernel,
                             cudaFuncAttributeMaxDynamicSharedMemorySize,
                             ATT_SMEM);
        attr_set = true;
    }
    const int gemm_smem = 8 * TILE_WORDS * 4;   // 81920 B

    split_f32_kernel<<<1024, 256>>>(x, xhi, xlo, M_ * C_);   // also resets g_ctr
    {
        dim3 grid(C3_ / 32, C_ / 32), blk(32, 8);
        split_transpose_kernel<<<grid, blk>>>(w_qkv, wqhi, wqlo, C_, C3_);
    }
    {
        dim3 grid(C_ / 32, C_ / 32), blk(32, 8);
        split_transpose_kernel<<<grid, blk>>>(w_out, wohi, wolo, C_, C_);
    }

    // 1) qkv = x @ w_qkv + b_qkv  -> hi/lo bf16  (persistent, ctr 0)
    gemm_bf16x2_kernel<<<GEMM_GRID, 128, gemm_smem>>>(
        xhi, xlo, wqhi, wqlo, b_qkv, nullptr, qkvhi, qkvlo, M_, C3_, C_, 0);

    // 2) causal attention -> y (hi/lo bf16)
    {
        dim3 grid(B_ * H_, T_ / 128);
        attn_mma_kernel<<<grid, 256, ATT_SMEM>>>(qkvhi, qkvlo, yhi, ylo);
    }

    // 3) out = y @ w_out + b_out  -> fp32  (persistent, ctr 1)
    gemm_bf16x2_kernel<<<GEMM_GRID, 128, gemm_smem>>>(
        yhi, ylo, wohi, wolo, b_out, out, nullptr, nullptr, M_, C_, C_, 1);
}

// round 10
// speedup vs baseline: 1.0340x; 1.0185x over previous
#include <cuda_runtime.h>
#include <cuda_bf16.h>
#include <math.h>
#include <stdint.h>

// Problem dims (fixed by the dataset)
#define B_   2
#define T_   2048
#define C_   1024
#define H_   16
#define HD_  64
#define C3_  (3*C_)
#define M_   (B_*T_)          // 4096 rows

// ---------------- scratch (no cudaMalloc allowed) ----------------
__device__ __nv_bfloat16 g_qkv_hi[(size_t)M_ * C3_];
__device__ __nv_bfloat16 g_qkv_lo[(size_t)M_ * C3_];
__device__ __nv_bfloat16 g_x_hi[(size_t)M_ * C_];
__device__ __nv_bfloat16 g_x_lo[(size_t)M_ * C_];
__device__ __nv_bfloat16 g_y_hi[(size_t)M_ * C_];
__device__ __nv_bfloat16 g_y_lo[(size_t)M_ * C_];
__device__ __nv_bfloat16 g_wqkvT_hi[(size_t)C3_ * C_];  // [N=3C][K=C]
__device__ __nv_bfloat16 g_wqkvT_lo[(size_t)C3_ * C_];
__device__ __nv_bfloat16 g_woutT_hi[(size_t)C_ * C_];   // [N=C][K=C]
__device__ __nv_bfloat16 g_woutT_lo[(size_t)C_ * C_];
__device__ int g_ctr[2];                                // persistent-GEMM tile counters

// ---------------- helpers ----------------
__device__ __forceinline__ uint32_t smem_u32(const void* p) {
    return (uint32_t)__cvta_generic_to_shared(p);
}
__device__ __forceinline__ void cp_async16(void* s, const void* g) {
    asm volatile("cp.async.cg.shared.global [%0], [%1], 16;\n"
                 :: "r"(smem_u32(s)), "l"(g));
}
__device__ __forceinline__ void cp_commit() {
    asm volatile("cp.async.commit_group;\n" ::);
}
__device__ __forceinline__ void cp_wait0() {
    asm volatile("cp.async.wait_group 0;\n" ::);
}
__device__ __forceinline__ void mma_bf16(float* d, const uint32_t* a, const uint32_t* b) {
    asm volatile(
        "mma.sync.aligned.m16n8k16.row.col.f32.bf16.bf16.f32 "
        "{%0,%1,%2,%3}, {%4,%5,%6,%7}, {%8,%9}, {%0,%1,%2,%3};\n"
        : "+f"(d[0]), "+f"(d[1]), "+f"(d[2]), "+f"(d[3])
        : "r"(a[0]), "r"(a[1]), "r"(a[2]), "r"(a[3]),
          "r"(b[0]), "r"(b[1]));
}
__device__ __forceinline__ void ldsm_x4(uint32_t* r, uint32_t addr) {
    asm volatile("ldmatrix.sync.aligned.m8n8.x4.shared.b16 {%0,%1,%2,%3}, [%4];"
                 : "=r"(r[0]), "=r"(r[1]), "=r"(r[2]), "=r"(r[3])
                 : "r"(addr));
}
__device__ __forceinline__ void ldsm_x4_trans(uint32_t* r, uint32_t addr) {
    asm volatile("ldmatrix.sync.aligned.m8n8.x4.trans.shared.b16 {%0,%1,%2,%3}, [%4];"
                 : "=r"(r[0]), "=r"(r[1]), "=r"(r[2]), "=r"(r[3])
                 : "r"(addr));
}
__device__ __forceinline__ uint32_t pack_bf16x2(float lo, float hi) {
    uint32_t r;
    asm("cvt.rn.bf16x2.f32 %0, %1, %2;" : "=r"(r) : "f"(hi), "f"(lo));
    return r;
}
__device__ __forceinline__ uint32_t pack_hi_pair(float a, float b,
                                                 float& ra, float& rb) {
    uint32_t w = pack_bf16x2(a, b);
    __nv_bfloat162 h = *reinterpret_cast<__nv_bfloat162*>(&w);
    ra = a - __bfloat162float(h.x);
    rb = b - __bfloat162float(h.y);
    return w;
}

// ---------------- fused prep kernel (one launch) ----------------
// blocks [0,256):       split x -> xhi/xlo (grid-stride)
// blocks [256,3328):    transpose+split w_qkv (96x32 tiles of 32x32)
// blocks [3328,4352):   transpose+split w_out (32x32 tiles)
#define PREP_GRID (256 + 3072 + 1024)

__global__ __launch_bounds__(256) void prep_kernel(
    const float* __restrict__ x,
    __nv_bfloat16* __restrict__ xhi, __nv_bfloat16* __restrict__ xlo,
    const float* __restrict__ wqkv,
    __nv_bfloat16* __restrict__ wqhi, __nv_bfloat16* __restrict__ wqlo,
    const float* __restrict__ wout,
    __nv_bfloat16* __restrict__ wohi, __nv_bfloat16* __restrict__ wolo)
{
    const int bid = blockIdx.x;
    const int t   = threadIdx.x;
    if (bid == 0 && t == 0) { g_ctr[0] = 0; g_ctr[1] = 0; }

    if (bid < 256) {
        const int n = M_ * C_;
        for (int i = bid * 256 + t; i < n; i += 256 * 256) {
            float v = x[i];
            __nv_bfloat16 h = __float2bfloat16(v);
            xhi[i] = h;
            xlo[i] = __float2bfloat16(v - __bfloat162float(h));
        }
        return;
    }

    __shared__ float ts[32][33];
    const float* src; __nv_bfloat16 *hi, *lo;
    int N, tileid, ncols;
    if (bid < 256 + 3072) {
        tileid = bid - 256;  src = wqkv; hi = wqhi; lo = wqlo;
        N = C3_; ncols = 96;
    } else {
        tileid = bid - 3328; src = wout; hi = wohi; lo = wolo;
        N = C_;  ncols = 32;
    }
    const int K  = C_;
    const int n0 = (tileid % ncols) * 32;
    const int k0 = (tileid / ncols) * 32;
    const int tx = t & 31;
    const int ty = t >> 5;
#pragma unroll
    for (int i = 0; i < 4; i++) {
        int k = k0 + ty + i * 8;
        ts[ty + i * 8][tx] = src[(size_t)k * N + n0 + tx];
    }
    __syncthreads();
#pragma unroll
    for (int i = 0; i < 4; i++) {
        int n = n0 + ty + i * 8;
        float v = ts[tx][ty + i * 8];
        __nv_bfloat16 h = __float2bfloat16(v);
        size_t idx = (size_t)n * K + k0 + tx;
        hi[idx] = h;
        lo[idx] = __float2bfloat16(v - __bfloat162float(h));
    }
}

// ================= persistent bf16 split-2 tensor-core GEMM =================
// C = A[M,K] @ W[K,N] + bias; A = (Ahi+Alo) bf16 [M][K], W = (Bhi+Blo) [N][K].
// D += Ahi*Bhi + Ahi*Blo + Alo*Bhi. Persistent CTAs + atomic tile stealing.
// 128 threads = 4 warps (2x2), warp tile 64x64.
#define GBM 128
#define GBN 128
#define GBK 32
#define TSTRIDE 20                     // uint32 words per SMEM tile row (80 B)
#define TILE_WORDS (128 * TSTRIDE)
#define GEMM_GRID 304                  // 2 CTAs x 152 SMs

__global__ __launch_bounds__(128, 2) void gemm_bf16x2_kernel(
    const __nv_bfloat16* __restrict__ Ahi, const __nv_bfloat16* __restrict__ Alo,
    const __nv_bfloat16* __restrict__ Bhi, const __nv_bfloat16* __restrict__ Blo,
    const float* __restrict__ bias,
    float* __restrict__ Cout,                     // fp32 path (if Chi==nullptr)
    __nv_bfloat16* __restrict__ Chi,              // hi/lo path
    __nv_bfloat16* __restrict__ Clo,
    int M, int N, int K, int ctr_slot)
{
    extern __shared__ uint32_t sm[];
    __shared__ int s_next;
    uint32_t* tiles[2][4];   // 0=Ahi 1=Alo 2=Bhi 3=Blo
#pragma unroll
    for (int b = 0; b < 2; b++)
#pragma unroll
        for (int t = 0; t < 4; t++)
            tiles[b][t] = sm + (b * 4 + t) * TILE_WORDS;

    const int tid  = threadIdx.x;
    const int wid  = tid >> 5;
    const int lane = tid & 31;
    const int g    = lane >> 2;
    const int q    = lane & 3;
    const int wm   = (wid & 1) * 64;
    const int wn   = (wid >> 1) * 64;

    const int grp = lane >> 3;
    const int rl  = lane & 7;
    uint32_t aRel[4];
#pragma unroll
    for (int mi = 0; mi < 4; mi++)
        aRel[mi] = (uint32_t)((wm + mi * 16 + (grp & 1) * 8 + rl) * 80
                              + (grp >> 1) * 16);
    uint32_t bRel[4];
#pragma unroll
    for (int ni2 = 0; ni2 < 4; ni2++)
        bRel[ni2] = (uint32_t)((wn + ni2 * 16 + (grp >> 1) * 8 + rl) * 80
                               + (grp & 1) * 16);

    const int ncol    = N / GBN;
    const int n_tiles = (M / GBM) * ncol;
    int ti = blockIdx.x;                       // implicit first tile

    while (ti < n_tiles) {
        const int row0 = (ti / ncol) * GBM;
        const int col0 = (ti % ncol) * GBN;

        float acc[4][8][4];
#pragma unroll
        for (int mi = 0; mi < 4; mi++)
#pragma unroll
            for (int ni = 0; ni < 8; ni++)
#pragma unroll
                for (int r = 0; r < 4; r++) acc[mi][ni][r] = 0.f;

        const __nv_bfloat16* srcs[4] = {Ahi, Alo, Bhi, Blo};
        auto load_tile = [&](int kt, int buf) {
            const int k0 = kt * GBK;
#pragma unroll
            for (int t = 0; t < 4; t++) {
                const __nv_bfloat16* base = srcs[t] +
                    (size_t)((t < 2) ? row0 : col0) * K + k0;
#pragma unroll
                for (int it = 0; it < 4; it++) {
                    int idx = tid + it * 128;       // 0..511
                    int r   = idx >> 2;
                    int f   = idx & 3;
                    cp_async16(&tiles[buf][t][r * TSTRIDE + f * 4],
                               base + (size_t)r * K + f * 8);
                }
            }
            cp_commit();
        };

        load_tile(0, 0);
        cp_wait0();
        __syncthreads();

        const int KT = K / GBK;
        for (int kt = 0; kt < KT; kt++) {
            const int buf = kt & 1;
            if (kt + 1 < KT) load_tile(kt + 1, buf ^ 1);

            const uint32_t baseAh = smem_u32(tiles[buf][0]);
            const uint32_t baseAl = smem_u32(tiles[buf][1]);
            const uint32_t baseBh = smem_u32(tiles[buf][2]);
            const uint32_t baseBl = smem_u32(tiles[buf][3]);

#pragma unroll
            for (int ks = 0; ks < 2; ks++) {
                const uint32_t ko = (uint32_t)ks * 32;
                uint32_t ah[4][4], al[4][4], bh[8][2], bl[8][2];
#pragma unroll
                for (int mi = 0; mi < 4; mi++) {
                    ldsm_x4(ah[mi], baseAh + aRel[mi] + ko);
                    ldsm_x4(al[mi], baseAl + aRel[mi] + ko);
                }
#pragma unroll
                for (int ni2 = 0; ni2 < 4; ni2++) {
                    uint32_t t4[4];
                    ldsm_x4(t4, baseBh + bRel[ni2] + ko);
                    bh[2*ni2][0] = t4[0]; bh[2*ni2][1] = t4[1];
                    bh[2*ni2+1][0] = t4[2]; bh[2*ni2+1][1] = t4[3];
                    ldsm_x4(t4, baseBl + bRel[ni2] + ko);
                    bl[2*ni2][0] = t4[0]; bl[2*ni2][1] = t4[1];
                    bl[2*ni2+1][0] = t4[2]; bl[2*ni2+1][1] = t4[3];
                }
#pragma unroll
                for (int mi = 0; mi < 4; mi++)
#pragma unroll
                    for (int ni = 0; ni < 8; ni++)
                        mma_bf16(acc[mi][ni], ah[mi], bh[ni]);
#pragma unroll
                for (int mi = 0; mi < 4; mi++)
#pragma unroll
                    for (int ni = 0; ni < 8; ni++)
                        mma_bf16(acc[mi][ni], ah[mi], bl[ni]);
#pragma unroll
                for (int mi = 0; mi < 4; mi++)
#pragma unroll
                    for (int ni = 0; ni < 8; ni++)
                        mma_bf16(acc[mi][ni], al[mi], bh[ni]);
            }

            if (kt + 1 < KT) cp_wait0();
            __syncthreads();
        }

        // ---- epilogue ----
#pragma unroll
        for (int mi = 0; mi < 4; mi++) {
#pragma unroll
            for (int ni = 0; ni < 8; ni++) {
                int r = row0 + wm + mi * 16 + g;
                int c = col0 + wn + ni * 8 + 2 * q;
                float b0 = bias[c], b1 = bias[c + 1];
                float v00 = acc[mi][ni][0] + b0, v01 = acc[mi][ni][1] + b1;
                float v10 = acc[mi][ni][2] + b0, v11 = acc[mi][ni][3] + b1;
                if (Chi) {
                    float r0, r1;
                    uint32_t hw0 = pack_hi_pair(v00, v01, r0, r1);
                    uint32_t lw0 = pack_bf16x2(r0, r1);
                    uint32_t hw1 = pack_hi_pair(v10, v11, r0, r1);
                    uint32_t lw1 = pack_bf16x2(r0, r1);
                    *(uint32_t*)(Chi + (size_t)r * N + c)       = hw0;
                    *(uint32_t*)(Clo + (size_t)r * N + c)       = lw0;
                    *(uint32_t*)(Chi + (size_t)(r + 8) * N + c) = hw1;
                    *(uint32_t*)(Clo + (size_t)(r + 8) * N + c) = lw1;
                } else {
                    *(float2*)(Cout + (size_t)r * N + c)       = make_float2(v00, v01);
                    *(float2*)(Cout + (size_t)(r + 8) * N + c) = make_float2(v10, v11);
                }
            }
        }

        // ---- grab next tile (work stealing) ----
        if (tid == 0) s_next = (int)gridDim.x + atomicAdd(&g_ctr[ctr_slot], 1);
        __syncthreads();
        ti = s_next;
        __syncthreads();   // keep s_next stable before next iteration's reuse
    }
}

// ================= MMA flash attention (bf16 hi/lo inputs, fp32 softmax) ========
// Block: 256 threads = 8 warps, 128 queries of one (b,h). 64-key tiles,
// double-buffered cp.async. K via ldmatrix, V via ldmatrix.trans.
// __launch_bounds__(256,2): force 2 CTAs/SM (regs <= 124) to cover barrier
// and load-latency gaps (kernel is latency-bound like the GEMM).
#define ATT_SMEM (2 * 9216 * 4)

__global__ __launch_bounds__(256, 2) void attn_mma_kernel(
    const __nv_bfloat16* __restrict__ qkvhi,
    const __nv_bfloat16* __restrict__ qkvlo,
    __nv_bfloat16* __restrict__ yhi, __nv_bfloat16* __restrict__ ylo)
{
    extern __shared__ uint32_t smd[];
    uint32_t* smB[2] = {smd, smd + 9216};

    const int tid  = threadIdx.x;
    const int w    = tid >> 5;
    const int lane = tid & 31;
    const int g    = lane >> 2;
    const int q    = lane & 3;
    const int grp  = lane >> 3;
    const int rl   = lane & 7;
    const int bh   = blockIdx.x;
    const int b    = bh >> 4;
    const int h    = bh & 15;
    const int qt   = (gridDim.y - 1) - blockIdx.y;   // heavy blocks first
    const int qb   = qt * 128;

    // ---- stage Q hi/lo into buffer 0, extract fragments, scale by 0.125 ----
#pragma unroll
    for (int it = 0; it < 8; it++) {
        int idx = tid + it * 256;            // 0..2047
        int arr = idx >> 10;                 // 0=hi,1=lo
        int rem = idx & 1023;
        int row = rem >> 3;
        int ch  = rem & 7;
        const __nv_bfloat16* src = (arr ? qkvlo : qkvhi)
            + (size_t)(b * T_ + qb + row) * C3_ + h * HD_ + ch * 8;
        cp_async16(&smB[0][arr * 4608 + row * 36 + ch * 4], src);
    }
    cp_commit();
    cp_wait0();
    __syncthreads();

    uint32_t qh[4][4], ql[4][4];
    {
        uint32_t qa = smem_u32(&smB[0][0])
            + (uint32_t)((w * 16 + (grp & 1) * 8 + rl) * 144 + (grp >> 1) * 16);
#pragma unroll
        for (int ks = 0; ks < 4; ks++) {
            ldsm_x4(qh[ks], qa + ks * 32);
            ldsm_x4(ql[ks], qa + 4608 * 4 + ks * 32);
        }
        const __nv_bfloat162 sc = __float2bfloat162_rn(0.125f);  // exact scale
#pragma unroll
        for (int ks = 0; ks < 4; ks++)
#pragma unroll
            for (int i = 0; i < 4; i++) {
                __nv_bfloat162 t = *(__nv_bfloat162*)&qh[ks][i];
                t = __hmul2(t, sc);
                qh[ks][i] = *(uint32_t*)&t;
                t = *(__nv_bfloat162*)&ql[ks][i];
                t = __hmul2(t, sc);
                ql[ks][i] = *(uint32_t*)&t;
            }
    }
    __syncthreads();   // buffer 0 free for K/V

    // K/V tile sources: [arr] 0=Khi 1=Klo 2=Vhi 3=Vlo
    const __nv_bfloat16* kv_src[4] = {
        qkvhi + C_, qkvlo + C_, qkvhi + 2 * C_, qkvlo + 2 * C_
    };
    auto load_tile = [&](int kt, int bufi) {
        const int k0 = kt * 64;
#pragma unroll
        for (int it = 0; it < 8; it++) {
            int idx = tid + it * 256;        // 0..2047
            int arr = idx >> 9;              // 0..3
            int rem = idx & 511;
            int row = rem >> 3;
            int ch  = rem & 7;
            const __nv_bfloat16* src = kv_src[arr]
                + (size_t)(b * T_ + k0 + row) * C3_ + h * HD_ + ch * 8;
            cp_async16(&smB[bufi][arr * 2304 + row * 36 + ch * 4], src);
        }
        cp_commit();
    };

    float o[8][4];
#pragma unroll
    for (int nj = 0; nj < 8; nj++)
#pragma unroll
        for (int c = 0; c < 4; c++) o[nj][c] = 0.f;
    float m0 = -INFINITY, m1 = -INFINITY;
    float l0 = 0.f, l1 = 0.f;

    const int qrow0 = qb + w * 16 + g;
    const int qrow1 = qrow0 + 8;
    const int qmax_w = qb + w * 16 + 15;
    const int kt_max = (qb + 127) >> 6;

    load_tile(0, 0);
    cp_wait0();
    __syncthreads();

    for (int kt = 0; kt <= kt_max; kt++) {
        const int bufi = kt & 1;
        const int k0 = kt * 64;
        if (kt + 1 <= kt_max) load_tile(kt + 1, bufi ^ 1);

        if (k0 <= qmax_w) {
            const uint32_t sb = smem_u32(&smB[bufi][0]);

            // ---- S = Q K^T (3-term split) ----
            float s[8][4];
#pragma unroll
            for (int ni2 = 0; ni2 < 4; ni2++) {
#pragma unroll
                for (int c = 0; c < 4; c++) {
                    s[2*ni2][c] = 0.f; s[2*ni2+1][c] = 0.f;
                }
                const uint32_t ka = sb
                    + (uint32_t)((ni2 * 16 + (grp >> 1) * 8 + rl) * 144
                                 + (grp & 1) * 16);
#pragma unroll
                for (int ks = 0; ks < 4; ks++) {
                    uint32_t bh4[4], bl4[4];
                    ldsm_x4(bh4, ka + ks * 32);
                    ldsm_x4(bl4, ka + 2304 * 4 + ks * 32);
                    mma_bf16(s[2*ni2],   qh[ks], bh4);
                    mma_bf16(s[2*ni2],   qh[ks], bl4);
                    mma_bf16(s[2*ni2],   ql[ks], bh4);
                    mma_bf16(s[2*ni2+1], qh[ks], bh4 + 2);
                    mma_bf16(s[2*ni2+1], qh[ks], bl4 + 2);
                    mma_bf16(s[2*ni2+1], ql[ks], bh4 + 2);
                }
            }

            // ---- causal mask ----
            if (k0 + 63 > qb + w * 16) {
#pragma unroll
                for (int ni = 0; ni < 8; ni++) {
                    int key = k0 + 8 * ni + 2 * q;
                    s[ni][0] = (key     <= qrow0) ? s[ni][0] : -INFINITY;
                    s[ni][1] = (key + 1 <= qrow0) ? s[ni][1] : -INFINITY;
                    s[ni][2] = (key     <= qrow1) ? s[ni][2] : -INFINITY;
                    s[ni][3] = (key + 1 <= qrow1) ? s[ni][3] : -INFINITY;
                }
            }

            // ---- online softmax ----
            float mx0 = s[0][0], mx1 = s[0][2];
#pragma unroll
            for (int ni = 0; ni < 8; ni++) {
                mx0 = fmaxf(mx0, fmaxf(s[ni][0], s[ni][1]));
                mx1 = fmaxf(mx1, fmaxf(s[ni][2], s[ni][3]));
            }
            mx0 = fmaxf(mx0, __shfl_xor_sync(0xffffffff, mx0, 1));
            mx0 = fmaxf(mx0, __shfl_xor_sync(0xffffffff, mx0, 2));
            mx1 = fmaxf(mx1, __shfl_xor_sync(0xffffffff, mx1, 1));
            mx1 = fmaxf(mx1, __shfl_xor_sync(0xffffffff, mx1, 2));

            float mn0 = fmaxf(m0, mx0), mn1 = fmaxf(m1, mx1);
            float al0 = __expf(m0 - mn0), al1 = __expf(m1 - mn1);
            m0 = mn0; m1 = mn1;
            l0 *= al0; l1 *= al1;
#pragma unroll
            for (int nj = 0; nj < 8; nj++) {
                o[nj][0] *= al0; o[nj][1] *= al0;
                o[nj][2] *= al1; o[nj][3] *= al1;
            }

            // ---- per k16 step: pack P, accumulate O += P V ----
#pragma unroll
            for (int ks = 0; ks < 4; ks++) {
                uint32_t af_hi[4], af_lo[4];
#pragma unroll
                for (int half = 0; half < 2; half++) {
                    const int ni = 2 * ks + half;
                    float p0 = __expf(s[ni][0] - mn0);
                    float p1 = __expf(s[ni][1] - mn0);
                    float p2 = __expf(s[ni][2] - mn1);
                    float p3 = __expf(s[ni][3] - mn1);
                    l0 += p0 + p1;
                    l1 += p2 + p3;
                    float r0, r1, r2, r3;
                    af_hi[2*half]     = pack_hi_pair(p0, p1, r0, r1);
                    af_lo[2*half]     = pack_bf16x2(r0, r1);
                    af_hi[2*half + 1] = pack_hi_pair(p2, p3, r2, r3);
                    af_lo[2*half + 1] = pack_bf16x2(r2, r3);
                }
                const uint32_t va = sb + 4608 * 4
                    + (uint32_t)((ks * 16 + (grp & 1) * 8 + rl) * 144
                                 + (grp >> 1) * 16);
#pragma unroll
                for (int nj2 = 0; nj2 < 4; nj2++) {
                    uint32_t vh4[4], vl4[4];
                    ldsm_x4_trans(vh4, va + nj2 * 32);
                    ldsm_x4_trans(vl4, va + 2304 * 4 + nj2 * 32);
                    mma_bf16(o[2*nj2],   af_hi, vh4);
                    mma_bf16(o[2*nj2],   af_hi, vl4);
                    mma_bf16(o[2*nj2],   af_lo, vh4);
                    mma_bf16(o[2*nj2+1], af_hi, vh4 + 2);
                    mma_bf16(o[2*nj2+1], af_hi, vl4 + 2);
                    mma_bf16(o[2*nj2+1], af_lo, vh4 + 2);
                }
            }
        }

        cp_wait0();
        __syncthreads();
    }

    // ---- epilogue ----
    l0 += __shfl_xor_sync(0xffffffff, l0, 1);
    l0 += __shfl_xor_sync(0xffffffff, l0, 2);
    l1 += __shfl_xor_sync(0xffffffff, l1, 1);
    l1 += __shfl_xor_sync(0xffffffff, l1, 2);
    const float inv0 = 1.f / l0;
    const float inv1 = 1.f / l1;

    __nv_bfloat16* yh0 = yhi + (size_t)(b * T_ + qrow0) * C_ + h * HD_;
    __nv_bfloat16* yl0 = ylo + (size_t)(b * T_ + qrow0) * C_ + h * HD_;
    __nv_bfloat16* yh1 = yhi + (size_t)(b * T_ + qrow1) * C_ + h * HD_;
    __nv_bfloat16* yl1 = ylo + (size_t)(b * T_ + qrow1) * C_ + h * HD_;
#pragma unroll
    for (int nj = 0; nj < 8; nj++) {
        int c = 8 * nj + 2 * q;
        float a0 = o[nj][0] * inv0, a1 = o[nj][1] * inv0;
        float a2 = o[nj][2] * inv1, a3 = o[nj][3] * inv1;
        float r0, r1, r2, r3;
        uint32_t h01 = pack_hi_pair(a0, a1, r0, r1);
        uint32_t h23 = pack_hi_pair(a2, a3, r2, r3);
        *(uint32_t*)(yh0 + c) = h01;
        *(uint32_t*)(yl0 + c) = pack_bf16x2(r0, r1);
        *(uint32_t*)(yh1 + c) = h23;
        *(uint32_t*)(yl1 + c) = pack_bf16x2(r2, r3);
    }
}

// ---------------- launch ----------------
extern "C" void kernel_launch(void* const* d_in, const int* in_sizes, int n_in,
                              void* d_out, int out_size)
{
    const float* x     = (const float*)d_in[0];
    const float* w_qkv = (const float*)d_in[1];
    const float* b_qkv = (const float*)d_in[2];
    const float* w_out = (const float*)d_in[3];
    const float* b_out = (const float*)d_in[4];
    float* out = (float*)d_out;

    __nv_bfloat16 *qkvhi, *qkvlo, *xhi, *xlo, *yhi, *ylo, *wqhi, *wqlo, *wohi, *wolo;
    cudaGetSymbolAddress((void**)&qkvhi, g_qkv_hi);
    cudaGetSymbolAddress((void**)&qkvlo, g_qkv_lo);
    cudaGetSymbolAddress((void**)&xhi, g_x_hi);
    cudaGetSymbolAddress((void**)&xlo, g_x_lo);
    cudaGetSymbolAddress((void**)&yhi, g_y_hi);
    cudaGetSymbolAddress((void**)&ylo, g_y_lo);
    cudaGetSymbolAddress((void**)&wqhi, g_wqkvT_hi);
    cudaGetSymbolAddress((void**)&wqlo, g_wqkvT_lo);
    cudaGetSymbolAddress((void**)&wohi, g_woutT_hi);
    cudaGetSymbolAddress((void**)&wolo, g_woutT_lo);

    static bool attr_set = false;
    if (!attr_set) {
        cudaFuncSetAttribute(gemm_bf16x2_kernel,
                             cudaFuncAttributeMaxDynamicSharedMemorySize,
                             8 * TILE_WORDS * 4);
        cudaFuncSetAttribute(attn_mma_kernel,
                             cudaFuncAttributeMaxDynamicSharedMemorySize,
                             ATT_SMEM);
        attr_set = true;
    }
    const int gemm_smem = 8 * TILE_WORDS * 4;   // 81920 B

    // 0) fused prep: split x, transpose+split both weights, reset counters
    prep_kernel<<<PREP_GRID, 256>>>(x, xhi, xlo,
                                    w_qkv, wqhi, wqlo,
                                    w_out, wohi, wolo);

    // 1) qkv = x @ w_qkv + b_qkv  -> hi/lo bf16  (persistent, ctr 0)
    gemm_bf16x2_kernel<<<GEMM_GRID, 128, gemm_smem>>>(
        xhi, xlo, wqhi, wqlo, b_qkv, nullptr, qkvhi, qkvlo, M_, C3_, C_, 0);

    // 2) causal attention -> y (hi/lo bf16)
    {
        dim3 grid(B_ * H_, T_ / 128);
        attn_mma_kernel<<<grid, 256, ATT_SMEM>>>(qkvhi, qkvlo, yhi, ylo);
    }

    // 3) out = y @ w_out + b_out  -> fp32  (persistent, ctr 1)
    gemm_bf16x2_kernel<<<GEMM_GRID, 128, gemm_smem>>>(
        yhi, ylo, wohi, wolo, b_out, out, nullptr, nullptr, M_, C_, C_, 1);
}

// round 11
// speedup vs baseline: 1.2169x; 1.1769x over previous
#include <cuda_runtime.h>
#include <cuda_bf16.h>
#include <cuda_fp16.h>
#include <math.h>
#include <stdint.h>

// Problem dims (fixed by the dataset)
#define B_   2
#define T_   2048
#define C_   1024
#define H_   16
#define HD_  64
#define C3_  (3*C_)
#define M_   (B_*T_)          // 4096 rows

// ---------------- scratch (no cudaMalloc allowed) ----------------
__device__ __nv_bfloat16 g_qkv_hi[(size_t)M_ * C3_];
__device__ __nv_bfloat16 g_qkv_lo[(size_t)M_ * C3_];
__device__ __half        g_x_hi[(size_t)M_ * C_];       // fp16 split of x
__device__ __half        g_x_lo[(size_t)M_ * C_];
__device__ __nv_bfloat16 g_y_hi[(size_t)M_ * C_];
__device__ __nv_bfloat16 g_y_lo[(size_t)M_ * C_];
__device__ __half        g_wqkvT_h[(size_t)C3_ * C_];   // [N=3C][K=C] single fp16
__device__ __nv_bfloat16 g_woutT_hi[(size_t)C_ * C_];   // [N=C][K=C]
__device__ __nv_bfloat16 g_woutT_lo[(size_t)C_ * C_];
__device__ int g_ctr[2];                                // persistent-GEMM tile counters

// ---------------- helpers ----------------
__device__ __forceinline__ uint32_t smem_u32(const void* p) {
    return (uint32_t)__cvta_generic_to_shared(p);
}
__device__ __forceinline__ void cp_async16(void* s, const void* g) {
    asm volatile("cp.async.cg.shared.global [%0], [%1], 16;\n"
                 :: "r"(smem_u32(s)), "l"(g));
}
__device__ __forceinline__ void cp_commit() {
    asm volatile("cp.async.commit_group;\n" ::);
}
__device__ __forceinline__ void cp_wait0() {
    asm volatile("cp.async.wait_group 0;\n" ::);
}
__device__ __forceinline__ void mma_bf16(float* d, const uint32_t* a, const uint32_t* b) {
    asm volatile(
        "mma.sync.aligned.m16n8k16.row.col.f32.bf16.bf16.f32 "
        "{%0,%1,%2,%3}, {%4,%5,%6,%7}, {%8,%9}, {%0,%1,%2,%3};\n"
        : "+f"(d[0]), "+f"(d[1]), "+f"(d[2]), "+f"(d[3])
        : "r"(a[0]), "r"(a[1]), "r"(a[2]), "r"(a[3]),
          "r"(b[0]), "r"(b[1]));
}
__device__ __forceinline__ void mma_f16(float* d, const uint32_t* a, const uint32_t* b) {
    asm volatile(
        "mma.sync.aligned.m16n8k16.row.col.f32.f16.f16.f32 "
        "{%0,%1,%2,%3}, {%4,%5,%6,%7}, {%8,%9}, {%0,%1,%2,%3};\n"
        : "+f"(d[0]), "+f"(d[1]), "+f"(d[2]), "+f"(d[3])
        : "r"(a[0]), "r"(a[1]), "r"(a[2]), "r"(a[3]),
          "r"(b[0]), "r"(b[1]));
}
__device__ __forceinline__ void ldsm_x4(uint32_t* r, uint32_t addr) {
    asm volatile("ldmatrix.sync.aligned.m8n8.x4.shared.b16 {%0,%1,%2,%3}, [%4];"
                 : "=r"(r[0]), "=r"(r[1]), "=r"(r[2]), "=r"(r[3])
                 : "r"(addr));
}
__device__ __forceinline__ void ldsm_x4_trans(uint32_t* r, uint32_t addr) {
    asm volatile("ldmatrix.sync.aligned.m8n8.x4.trans.shared.b16 {%0,%1,%2,%3}, [%4];"
                 : "=r"(r[0]), "=r"(r[1]), "=r"(r[2]), "=r"(r[3])
                 : "r"(addr));
}
__device__ __forceinline__ uint32_t pack_bf16x2(float lo, float hi) {
    uint32_t r;
    asm("cvt.rn.bf16x2.f32 %0, %1, %2;" : "=r"(r) : "f"(hi), "f"(lo));
    return r;
}
__device__ __forceinline__ uint32_t pack_hi_pair(float a, float b,
                                                 float& ra, float& rb) {
    uint32_t w = pack_bf16x2(a, b);
    __nv_bfloat162 h = *reinterpret_cast<__nv_bfloat162*>(&w);
    ra = a - __bfloat162float(h.x);
    rb = b - __bfloat162float(h.y);
    return w;
}

// ---------------- fused prep kernel (one launch) ----------------
// blocks [0,256):       split x -> fp16 xhi/xlo (grid-stride)
// blocks [256,3328):    transpose w_qkv -> fp16 (96x32 tiles of 32x32)
// blocks [3328,4352):   transpose+split w_out -> bf16 hi/lo (32x32 tiles)
#define PREP_GRID (256 + 3072 + 1024)

__global__ __launch_bounds__(256) void prep_kernel(
    const float* __restrict__ x,
    __half* __restrict__ xhi, __half* __restrict__ xlo,
    const float* __restrict__ wqkv, __half* __restrict__ wq,
    const float* __restrict__ wout,
    __nv_bfloat16* __restrict__ wohi, __nv_bfloat16* __restrict__ wolo)
{
    const int bid = blockIdx.x;
    const int t   = threadIdx.x;
    if (bid == 0 && t == 0) { g_ctr[0] = 0; g_ctr[1] = 0; }

    if (bid < 256) {
        const int n = M_ * C_;
        for (int i = bid * 256 + t; i < n; i += 256 * 256) {
            float v = x[i];
            __half h = __float2half_rn(v);
            xhi[i] = h;
            xlo[i] = __float2half_rn(v - __half2float(h));
        }
        return;
    }

    __shared__ float ts[32][33];
    const int tx = t & 31;
    const int ty = t >> 5;
    const int K  = C_;

    if (bid < 256 + 3072) {
        const int tileid = bid - 256;
        const int N  = C3_;
        const int n0 = (tileid % 96) * 32;
        const int k0 = (tileid / 96) * 32;
#pragma unroll
        for (int i = 0; i < 4; i++) {
            int k = k0 + ty + i * 8;
            ts[ty + i * 8][tx] = wqkv[(size_t)k * N + n0 + tx];
        }
        __syncthreads();
#pragma unroll
        for (int i = 0; i < 4; i++) {
            int n = n0 + ty + i * 8;
            wq[(size_t)n * K + k0 + tx] = __float2half_rn(ts[tx][ty + i * 8]);
        }
    } else {
        const int tileid = bid - 3328;
        const int N  = C_;
        const int n0 = (tileid % 32) * 32;
        const int k0 = (tileid / 32) * 32;
#pragma unroll
        for (int i = 0; i < 4; i++) {
            int k = k0 + ty + i * 8;
            ts[ty + i * 8][tx] = wout[(size_t)k * N + n0 + tx];
        }
        __syncthreads();
#pragma unroll
        for (int i = 0; i < 4; i++) {
            int n = n0 + ty + i * 8;
            float v = ts[tx][ty + i * 8];
            __nv_bfloat16 h = __float2bfloat16(v);
            size_t idx = (size_t)n * K + k0 + tx;
            wohi[idx] = h;
            wolo[idx] = __float2bfloat16(v - __bfloat162float(h));
        }
    }
}

// shared GEMM geometry
#define GBM 128
#define GBN 128
#define GBK 32
#define TSTRIDE 20                     // uint32 words per SMEM tile row (80 B)
#define TILE_WORDS (128 * TSTRIDE)
#define GEMM_GRID 304                  // 2 CTAs x 152 SMs

// ================= fp16 2-term persistent GEMM (QKV) =================
// D = (Ahi + Alo)[M,K] @ B^T + bias; A split fp16, B single fp16 [N][K].
// Output: bf16 hi/lo. 128 threads = 4 warps (2x2), warp tile 64x64.
__global__ __launch_bounds__(128, 2) void gemm_f16x2_kernel(
    const __half* __restrict__ Ahi, const __half* __restrict__ Alo,
    const __half* __restrict__ Bw,
    const float* __restrict__ bias,
    __nv_bfloat16* __restrict__ Chi, __nv_bfloat16* __restrict__ Clo,
    int M, int N, int K, int ctr_slot)
{
    extern __shared__ uint32_t sm[];
    __shared__ int s_next;
    uint32_t* tiles[2][3];   // 0=Ahi 1=Alo 2=B
#pragma unroll
    for (int b = 0; b < 2; b++)
#pragma unroll
        for (int t = 0; t < 3; t++)
            tiles[b][t] = sm + (b * 3 + t) * TILE_WORDS;

    const int tid  = threadIdx.x;
    const int wid  = tid >> 5;
    const int lane = tid & 31;
    const int g    = lane >> 2;
    const int q    = lane & 3;
    const int wm   = (wid & 1) * 64;
    const int wn   = (wid >> 1) * 64;

    const int grp = lane >> 3;
    const int rl  = lane & 7;
    uint32_t aRel[4];
#pragma unroll
    for (int mi = 0; mi < 4; mi++)
        aRel[mi] = (uint32_t)((wm + mi * 16 + (grp & 1) * 8 + rl) * 80
                              + (grp >> 1) * 16);
    uint32_t bRel[4];
#pragma unroll
    for (int ni2 = 0; ni2 < 4; ni2++)
        bRel[ni2] = (uint32_t)((wn + ni2 * 16 + (grp >> 1) * 8 + rl) * 80
                               + (grp & 1) * 16);

    const int ncol    = N / GBN;
    const int n_tiles = (M / GBM) * ncol;
    int ti = blockIdx.x;

    while (ti < n_tiles) {
        const int row0 = (ti / ncol) * GBM;
        const int col0 = (ti % ncol) * GBN;

        float acc[4][8][4];
#pragma unroll
        for (int mi = 0; mi < 4; mi++)
#pragma unroll
            for (int ni = 0; ni < 8; ni++)
#pragma unroll
                for (int r = 0; r < 4; r++) acc[mi][ni][r] = 0.f;

        const __half* srcs[3] = {Ahi, Alo, Bw};
        auto load_tile = [&](int kt, int buf) {
            const int k0 = kt * GBK;
#pragma unroll
            for (int t = 0; t < 3; t++) {
                const __half* base = srcs[t] +
                    (size_t)((t < 2) ? row0 : col0) * K + k0;
#pragma unroll
                for (int it = 0; it < 4; it++) {
                    int idx = tid + it * 128;       // 0..511
                    int r   = idx >> 2;
                    int f   = idx & 3;
                    cp_async16(&tiles[buf][t][r * TSTRIDE + f * 4],
                               base + (size_t)r * K + f * 8);
                }
            }
            cp_commit();
        };

        load_tile(0, 0);
        cp_wait0();
        __syncthreads();

        const int KT = K / GBK;
        for (int kt = 0; kt < KT; kt++) {
            const int buf = kt & 1;
            if (kt + 1 < KT) load_tile(kt + 1, buf ^ 1);

            const uint32_t baseAh = smem_u32(tiles[buf][0]);
            const uint32_t baseAl = smem_u32(tiles[buf][1]);
            const uint32_t baseB  = smem_u32(tiles[buf][2]);

#pragma unroll
            for (int ks = 0; ks < 2; ks++) {
                const uint32_t ko = (uint32_t)ks * 32;
                uint32_t ah[4][4], al[4][4], bf[8][2];
#pragma unroll
                for (int mi = 0; mi < 4; mi++) {
                    ldsm_x4(ah[mi], baseAh + aRel[mi] + ko);
                    ldsm_x4(al[mi], baseAl + aRel[mi] + ko);
                }
#pragma unroll
                for (int ni2 = 0; ni2 < 4; ni2++) {
                    uint32_t t4[4];
                    ldsm_x4(t4, baseB + bRel[ni2] + ko);
                    bf[2*ni2][0] = t4[0]; bf[2*ni2][1] = t4[1];
                    bf[2*ni2+1][0] = t4[2]; bf[2*ni2+1][1] = t4[3];
                }
#pragma unroll
                for (int mi = 0; mi < 4; mi++)
#pragma unroll
                    for (int ni = 0; ni < 8; ni++)
                        mma_f16(acc[mi][ni], ah[mi], bf[ni]);
#pragma unroll
                for (int mi = 0; mi < 4; mi++)
#pragma unroll
                    for (int ni = 0; ni < 8; ni++)
                        mma_f16(acc[mi][ni], al[mi], bf[ni]);
            }

            if (kt + 1 < KT) cp_wait0();
            __syncthreads();
        }

        // ---- epilogue: bias + bf16 hi/lo store ----
#pragma unroll
        for (int mi = 0; mi < 4; mi++) {
#pragma unroll
            for (int ni = 0; ni < 8; ni++) {
                int r = row0 + wm + mi * 16 + g;
                int c = col0 + wn + ni * 8 + 2 * q;
                float b0 = bias[c], b1 = bias[c + 1];
                float v00 = acc[mi][ni][0] + b0, v01 = acc[mi][ni][1] + b1;
                float v10 = acc[mi][ni][2] + b0, v11 = acc[mi][ni][3] + b1;
                float r0, r1;
                uint32_t hw0 = pack_hi_pair(v00, v01, r0, r1);
                uint32_t lw0 = pack_bf16x2(r0, r1);
                uint32_t hw1 = pack_hi_pair(v10, v11, r0, r1);
                uint32_t lw1 = pack_bf16x2(r0, r1);
                *(uint32_t*)(Chi + (size_t)r * N + c)       = hw0;
                *(uint32_t*)(Clo + (size_t)r * N + c)       = lw0;
                *(uint32_t*)(Chi + (size_t)(r + 8) * N + c) = hw1;
                *(uint32_t*)(Clo + (size_t)(r + 8) * N + c) = lw1;
            }
        }

        if (tid == 0) s_next = (int)gridDim.x + atomicAdd(&g_ctr[ctr_slot], 1);
        __syncthreads();
        ti = s_next;
        __syncthreads();
    }
}

// ================= bf16 3-term persistent GEMM (out-proj) =================
__global__ __launch_bounds__(128, 2) void gemm_bf16x2_kernel(
    const __nv_bfloat16* __restrict__ Ahi, const __nv_bfloat16* __restrict__ Alo,
    const __nv_bfloat16* __restrict__ Bhi, const __nv_bfloat16* __restrict__ Blo,
    const float* __restrict__ bias,
    float* __restrict__ Cout,
    int M, int N, int K, int ctr_slot)
{
    extern __shared__ uint32_t sm[];
    __shared__ int s_next;
    uint32_t* tiles[2][4];
#pragma unroll
    for (int b = 0; b < 2; b++)
#pragma unroll
        for (int t = 0; t < 4; t++)
            tiles[b][t] = sm + (b * 4 + t) * TILE_WORDS;

    const int tid  = threadIdx.x;
    const int wid  = tid >> 5;
    const int lane = tid & 31;
    const int g    = lane >> 2;
    const int q    = lane & 3;
    const int wm   = (wid & 1) * 64;
    const int wn   = (wid >> 1) * 64;

    const int grp = lane >> 3;
    const int rl  = lane & 7;
    uint32_t aRel[4];
#pragma unroll
    for (int mi = 0; mi < 4; mi++)
        aRel[mi] = (uint32_t)((wm + mi * 16 + (grp & 1) * 8 + rl) * 80
                              + (grp >> 1) * 16);
    uint32_t bRel[4];
#pragma unroll
    for (int ni2 = 0; ni2 < 4; ni2++)
        bRel[ni2] = (uint32_t)((wn + ni2 * 16 + (grp >> 1) * 8 + rl) * 80
                               + (grp & 1) * 16);

    const int ncol    = N / GBN;
    const int n_tiles = (M / GBM) * ncol;
    int ti = blockIdx.x;

    while (ti < n_tiles) {
        const int row0 = (ti / ncol) * GBM;
        const int col0 = (ti % ncol) * GBN;

        float acc[4][8][4];
#pragma unroll
        for (int mi = 0; mi < 4; mi++)
#pragma unroll
            for (int ni = 0; ni < 8; ni++)
#pragma unroll
                for (int r = 0; r < 4; r++) acc[mi][ni][r] = 0.f;

        const __nv_bfloat16* srcs[4] = {Ahi, Alo, Bhi, Blo};
        auto load_tile = [&](int kt, int buf) {
            const int k0 = kt * GBK;
#pragma unroll
            for (int t = 0; t < 4; t++) {
                const __nv_bfloat16* base = srcs[t] +
                    (size_t)((t < 2) ? row0 : col0) * K + k0;
#pragma unroll
                for (int it = 0; it < 4; it++) {
                    int idx = tid + it * 128;
                    int r   = idx >> 2;
                    int f   = idx & 3;
                    cp_async16(&tiles[buf][t][r * TSTRIDE + f * 4],
                               base + (size_t)r * K + f * 8);
                }
            }
            cp_commit();
        };

        load_tile(0, 0);
        cp_wait0();
        __syncthreads();

        const int KT = K / GBK;
        for (int kt = 0; kt < KT; kt++) {
            const int buf = kt & 1;
            if (kt + 1 < KT) load_tile(kt + 1, buf ^ 1);

            const uint32_t baseAh = smem_u32(tiles[buf][0]);
            const uint32_t baseAl = smem_u32(tiles[buf][1]);
            const uint32_t baseBh = smem_u32(tiles[buf][2]);
            const uint32_t baseBl = smem_u32(tiles[buf][3]);

#pragma unroll
            for (int ks = 0; ks < 2; ks++) {
                const uint32_t ko = (uint32_t)ks * 32;
                uint32_t ah[4][4], al[4][4], bh[8][2], bl[8][2];
#pragma unroll
                for (int mi = 0; mi < 4; mi++) {
                    ldsm_x4(ah[mi], baseAh + aRel[mi] + ko);
                    ldsm_x4(al[mi], baseAl + aRel[mi] + ko);
                }
#pragma unroll
                for (int ni2 = 0; ni2 < 4; ni2++) {
                    uint32_t t4[4];
                    ldsm_x4(t4, baseBh + bRel[ni2] + ko);
                    bh[2*ni2][0] = t4[0]; bh[2*ni2][1] = t4[1];
                    bh[2*ni2+1][0] = t4[2]; bh[2*ni2+1][1] = t4[3];
                    ldsm_x4(t4, baseBl + bRel[ni2] + ko);
                    bl[2*ni2][0] = t4[0]; bl[2*ni2][1] = t4[1];
                    bl[2*ni2+1][0] = t4[2]; bl[2*ni2+1][1] = t4[3];
                }
#pragma unroll
                for (int mi = 0; mi < 4; mi++)
#pragma unroll
                    for (int ni = 0; ni < 8; ni++)
                        mma_bf16(acc[mi][ni], ah[mi], bh[ni]);
#pragma unroll
                for (int mi = 0; mi < 4; mi++)
#pragma unroll
                    for (int ni = 0; ni < 8; ni++)
                        mma_bf16(acc[mi][ni], ah[mi], bl[ni]);
#pragma unroll
                for (int mi = 0; mi < 4; mi++)
#pragma unroll
                    for (int ni = 0; ni < 8; ni++)
                        mma_bf16(acc[mi][ni], al[mi], bh[ni]);
            }

            if (kt + 1 < KT) cp_wait0();
            __syncthreads();
        }

#pragma unroll
        for (int mi = 0; mi < 4; mi++) {
#pragma unroll
            for (int ni = 0; ni < 8; ni++) {
                int r = row0 + wm + mi * 16 + g;
                int c = col0 + wn + ni * 8 + 2 * q;
                float b0 = bias[c], b1 = bias[c + 1];
                *(float2*)(Cout + (size_t)r * N + c) =
                    make_float2(acc[mi][ni][0] + b0, acc[mi][ni][1] + b1);
                *(float2*)(Cout + (size_t)(r + 8) * N + c) =
                    make_float2(acc[mi][ni][2] + b0, acc[mi][ni][3] + b1);
            }
        }

        if (tid == 0) s_next = (int)gridDim.x + atomicAdd(&g_ctr[ctr_slot], 1);
        __syncthreads();
        ti = s_next;
        __syncthreads();
    }
}

// ================= MMA flash attention (bf16 hi/lo inputs, fp32 softmax) ========
#define ATT_SMEM (2 * 9216 * 4)

__global__ __launch_bounds__(256, 2) void attn_mma_kernel(
    const __nv_bfloat16* __restrict__ qkvhi,
    const __nv_bfloat16* __restrict__ qkvlo,
    __nv_bfloat16* __restrict__ yhi, __nv_bfloat16* __restrict__ ylo)
{
    extern __shared__ uint32_t smd[];
    uint32_t* smB[2] = {smd, smd + 9216};

    const int tid  = threadIdx.x;
    const int w    = tid >> 5;
    const int lane = tid & 31;
    const int g    = lane >> 2;
    const int q    = lane & 3;
    const int grp  = lane >> 3;
    const int rl   = lane & 7;
    const int bh   = blockIdx.x;
    const int b    = bh >> 4;
    const int h    = bh & 15;
    const int qt   = (gridDim.y - 1) - blockIdx.y;   // heavy blocks first
    const int qb   = qt * 128;

#pragma unroll
    for (int it = 0; it < 8; it++) {
        int idx = tid + it * 256;
        int arr = idx >> 10;
        int rem = idx & 1023;
        int row = rem >> 3;
        int ch  = rem & 7;
        const __nv_bfloat16* src = (arr ? qkvlo : qkvhi)
            + (size_t)(b * T_ + qb + row) * C3_ + h * HD_ + ch * 8;
        cp_async16(&smB[0][arr * 4608 + row * 36 + ch * 4], src);
    }
    cp_commit();
    cp_wait0();
    __syncthreads();

    uint32_t qh[4][4], ql[4][4];
    {
        uint32_t qa = smem_u32(&smB[0][0])
            + (uint32_t)((w * 16 + (grp & 1) * 8 + rl) * 144 + (grp >> 1) * 16);
#pragma unroll
        for (int ks = 0; ks < 4; ks++) {
            ldsm_x4(qh[ks], qa + ks * 32);
            ldsm_x4(ql[ks], qa + 4608 * 4 + ks * 32);
        }
        const __nv_bfloat162 sc = __float2bfloat162_rn(0.125f);
#pragma unroll
        for (int ks = 0; ks < 4; ks++)
#pragma unroll
            for (int i = 0; i < 4; i++) {
                __nv_bfloat162 t = *(__nv_bfloat162*)&qh[ks][i];
                t = __hmul2(t, sc);
                qh[ks][i] = *(uint32_t*)&t;
                t = *(__nv_bfloat162*)&ql[ks][i];
                t = __hmul2(t, sc);
                ql[ks][i] = *(uint32_t*)&t;
            }
    }
    __syncthreads();

    const __nv_bfloat16* kv_src[4] = {
        qkvhi + C_, qkvlo + C_, qkvhi + 2 * C_, qkvlo + 2 * C_
    };
    auto load_tile = [&](int kt, int bufi) {
        const int k0 = kt * 64;
#pragma unroll
        for (int it = 0; it < 8; it++) {
            int idx = tid + it * 256;
            int arr = idx >> 9;
            int rem = idx & 511;
            int row = rem >> 3;
            int ch  = rem & 7;
            const __nv_bfloat16* src = kv_src[arr]
                + (size_t)(b * T_ + k0 + row) * C3_ + h * HD_ + ch * 8;
            cp_async16(&smB[bufi][arr * 2304 + row * 36 + ch * 4], src);
        }
        cp_commit();
    };

    float o[8][4];
#pragma unroll
    for (int nj = 0; nj < 8; nj++)
#pragma unroll
        for (int c = 0; c < 4; c++) o[nj][c] = 0.f;
    float m0 = -INFINITY, m1 = -INFINITY;
    float l0 = 0.f, l1 = 0.f;

    const int qrow0 = qb + w * 16 + g;
    const int qrow1 = qrow0 + 8;
    const int qmax_w = qb + w * 16 + 15;
    const int kt_max = (qb + 127) >> 6;

    load_tile(0, 0);
    cp_wait0();
    __syncthreads();

    for (int kt = 0; kt <= kt_max; kt++) {
        const int bufi = kt & 1;
        const int k0 = kt * 64;
        if (kt + 1 <= kt_max) load_tile(kt + 1, bufi ^ 1);

        if (k0 <= qmax_w) {
            const uint32_t sb = smem_u32(&smB[bufi][0]);

            float s[8][4];
#pragma unroll
            for (int ni2 = 0; ni2 < 4; ni2++) {
#pragma unroll
                for (int c = 0; c < 4; c++) {
                    s[2*ni2][c] = 0.f; s[2*ni2+1][c] = 0.f;
                }
                const uint32_t ka = sb
                    + (uint32_t)((ni2 * 16 + (grp >> 1) * 8 + rl) * 144
                                 + (grp & 1) * 16);
#pragma unroll
                for (int ks = 0; ks < 4; ks++) {
                    uint32_t bh4[4], bl4[4];
                    ldsm_x4(bh4, ka + ks * 32);
                    ldsm_x4(bl4, ka + 2304 * 4 + ks * 32);
                    mma_bf16(s[2*ni2],   qh[ks], bh4);
                    mma_bf16(s[2*ni2],   qh[ks], bl4);
                    mma_bf16(s[2*ni2],   ql[ks], bh4);
                    mma_bf16(s[2*ni2+1], qh[ks], bh4 + 2);
                    mma_bf16(s[2*ni2+1], qh[ks], bl4 + 2);
                    mma_bf16(s[2*ni2+1], ql[ks], bh4 + 2);
                }
            }

            if (k0 + 63 > qb + w * 16) {
#pragma unroll
                for (int ni = 0; ni < 8; ni++) {
                    int key = k0 + 8 * ni + 2 * q;
                    s[ni][0] = (key     <= qrow0) ? s[ni][0] : -INFINITY;
                    s[ni][1] = (key + 1 <= qrow0) ? s[ni][1] : -INFINITY;
                    s[ni][2] = (key     <= qrow1) ? s[ni][2] : -INFINITY;
                    s[ni][3] = (key + 1 <= qrow1) ? s[ni][3] : -INFINITY;
                }
            }

            float mx0 = s[0][0], mx1 = s[0][2];
#pragma unroll
            for (int ni = 0; ni < 8; ni++) {
                mx0 = fmaxf(mx0, fmaxf(s[ni][0], s[ni][1]));
                mx1 = fmaxf(mx1, fmaxf(s[ni][2], s[ni][3]));
            }
            mx0 = fmaxf(mx0, __shfl_xor_sync(0xffffffff, mx0, 1));
            mx0 = fmaxf(mx0, __shfl_xor_sync(0xffffffff, mx0, 2));
            mx1 = fmaxf(mx1, __shfl_xor_sync(0xffffffff, mx1, 1));
            mx1 = fmaxf(mx1, __shfl_xor_sync(0xffffffff, mx1, 2));

            float mn0 = fmaxf(m0, mx0), mn1 = fmaxf(m1, mx1);
            float al0 = __expf(m0 - mn0), al1 = __expf(m1 - mn1);
            m0 = mn0; m1 = mn1;
            l0 *= al0; l1 *= al1;
#pragma unroll
            for (int nj = 0; nj < 8; nj++) {
                o[nj][0] *= al0; o[nj][1] *= al0;
                o[nj][2] *= al1; o[nj][3] *= al1;
            }

#pragma unroll
            for (int ks = 0; ks < 4; ks++) {
                uint32_t af_hi[4], af_lo[4];
#pragma unroll
                for (int half = 0; half < 2; half++) {
                    const int ni = 2 * ks + half;
                    float p0 = __expf(s[ni][0] - mn0);
                    float p1 = __expf(s[ni][1] - mn0);
                    float p2 = __expf(s[ni][2] - mn1);
                    float p3 = __expf(s[ni][3] - mn1);
                    l0 += p0 + p1;
                    l1 += p2 + p3;
                    float r0, r1, r2, r3;
                    af_hi[2*half]     = pack_hi_pair(p0, p1, r0, r1);
                    af_lo[2*half]     = pack_bf16x2(r0, r1);
                    af_hi[2*half + 1] = pack_hi_pair(p2, p3, r2, r3);
                    af_lo[2*half + 1] = pack_bf16x2(r2, r3);
                }
                const uint32_t va = sb + 4608 * 4
                    + (uint32_t)((ks * 16 + (grp & 1) * 8 + rl) * 144
                                 + (grp >> 1) * 16);
#pragma unroll
                for (int nj2 = 0; nj2 < 4; nj2++) {
                    uint32_t vh4[4], vl4[4];
                    ldsm_x4_trans(vh4, va + nj2 * 32);
                    ldsm_x4_trans(vl4, va + 2304 * 4 + nj2 * 32);
                    mma_bf16(o[2*nj2],   af_hi, vh4);
                    mma_bf16(o[2*nj2],   af_hi, vl4);
                    mma_bf16(o[2*nj2],   af_lo, vh4);
                    mma_bf16(o[2*nj2+1], af_hi, vh4 + 2);
                    mma_bf16(o[2*nj2+1], af_hi, vl4 + 2);
                    mma_bf16(o[2*nj2+1], af_lo, vh4 + 2);
                }
            }
        }

        cp_wait0();
        __syncthreads();
    }

    l0 += __shfl_xor_sync(0xffffffff, l0, 1);
    l0 += __shfl_xor_sync(0xffffffff, l0, 2);
    l1 += __shfl_xor_sync(0xffffffff, l1, 1);
    l1 += __shfl_xor_sync(0xffffffff, l1, 2);
    const float inv0 = 1.f / l0;
    const float inv1 = 1.f / l1;

    __nv_bfloat16* yh0 = yhi + (size_t)(b * T_ + qrow0) * C_ + h * HD_;
    __nv_bfloat16* yl0 = ylo + (size_t)(b * T_ + qrow0) * C_ + h * HD_;
    __nv_bfloat16* yh1 = yhi + (size_t)(b * T_ + qrow1) * C_ + h * HD_;
    __nv_bfloat16* yl1 = ylo + (size_t)(b * T_ + qrow1) * C_ + h * HD_;
#pragma unroll
    for (int nj = 0; nj < 8; nj++) {
        int c = 8 * nj + 2 * q;
        float a0 = o[nj][0] * inv0, a1 = o[nj][1] * inv0;
        float a2 = o[nj][2] * inv1, a3 = o[nj][3] * inv1;
        float r0, r1, r2, r3;
        uint32_t h01 = pack_hi_pair(a0, a1, r0, r1);
        uint32_t h23 = pack_hi_pair(a2, a3, r2, r3);
        *(uint32_t*)(yh0 + c) = h01;
        *(uint32_t*)(yl0 + c) = pack_bf16x2(r0, r1);
        *(uint32_t*)(yh1 + c) = h23;
        *(uint32_t*)(yl1 + c) = pack_bf16x2(r2, r3);
    }
}

// ---------------- launch ----------------
extern "C" void kernel_launch(void* const* d_in, const int* in_sizes, int n_in,
                              void* d_out, int out_size)
{
    const float* x     = (const float*)d_in[0];
    const float* w_qkv = (const float*)d_in[1];
    const float* b_qkv = (const float*)d_in[2];
    const float* w_out = (const float*)d_in[3];
    const float* b_out = (const float*)d_in[4];
    float* out = (float*)d_out;

    __nv_bfloat16 *qkvhi, *qkvlo, *yhi, *ylo, *wohi, *wolo;
    __half *xhi, *xlo, *wq;
    cudaGetSymbolAddress((void**)&qkvhi, g_qkv_hi);
    cudaGetSymbolAddress((void**)&qkvlo, g_qkv_lo);
    cudaGetSymbolAddress((void**)&xhi, g_x_hi);
    cudaGetSymbolAddress((void**)&xlo, g_x_lo);
    cudaGetSymbolAddress((void**)&yhi, g_y_hi);
    cudaGetSymbolAddress((void**)&ylo, g_y_lo);
    cudaGetSymbolAddress((void**)&wq, g_wqkvT_h);
    cudaGetSymbolAddress((void**)&wohi, g_woutT_hi);
    cudaGetSymbolAddress((void**)&wolo, g_woutT_lo);

    static bool attr_set = false;
    if (!attr_set) {
        cudaFuncSetAttribute(gemm_f16x2_kernel,
                             cudaFuncAttributeMaxDynamicSharedMemorySize,
                             6 * TILE_WORDS * 4);
        cudaFuncSetAttribute(gemm_bf16x2_kernel,
                             cudaFuncAttributeMaxDynamicSharedMemorySize,
                             8 * TILE_WORDS * 4);
        cudaFuncSetAttribute(attn_mma_kernel,
                             cudaFuncAttributeMaxDynamicSharedMemorySize,
                             ATT_SMEM);
        attr_set = true;
    }
    const int gemm_f16_smem  = 6 * TILE_WORDS * 4;   // 61440 B
    const int gemm_bf16_smem = 8 * TILE_WORDS * 4;   // 81920 B

    // 0) fused prep
    prep_kernel<<<PREP_GRID, 256>>>(x, xhi, xlo, w_qkv, wq,
                                    w_out, wohi, wolo);

    // 1) qkv = x @ w_qkv + b_qkv  (fp16 2-term)  -> bf16 hi/lo
    gemm_f16x2_kernel<<<GEMM_GRID, 128, gemm_f16_smem>>>(
        xhi, xlo, wq, b_qkv, qkvhi, qkvlo, M_, C3_, C_, 0);

    // 2) causal attention -> y (bf16 hi/lo)
    {
        dim3 grid(B_ * H_, T_ / 128);
        attn_mma_kernel<<<grid, 256, ATT_SMEM>>>(qkvhi, qkvlo, yhi, ylo);
    }

    // 3) out = y @ w_out + b_out  (bf16 3-term)  -> fp32
    gemm_bf16x2_kernel<<<GEMM_GRID, 128, gemm_bf16_smem>>>(
        yhi, ylo, wohi, wolo, b_out, out, M_, C_, C_, 1);
}

// round 12
// speedup vs baseline: 1.4488x; 1.1906x over previous
#include <cuda_runtime.h>
#include <cuda_bf16.h>
#include <cuda_fp16.h>
#include <math.h>
#include <stdint.h>

// Problem dims (fixed by the dataset)
#define B_   2
#define T_   2048
#define C_   1024
#define H_   16
#define HD_  64
#define C3_  (3*C_)
#define M_   (B_*T_)          // 4096 rows

// ---------------- scratch (no cudaMalloc allowed) ----------------
__device__ __half g_qkv_hi[(size_t)M_ * C3_];   // fp16 split of qkv
__device__ __half g_qkv_lo[(size_t)M_ * C3_];
__device__ __half g_x_hi[(size_t)M_ * C_];      // fp16 split of x
__device__ __half g_x_lo[(size_t)M_ * C_];
__device__ __half g_y_hi[(size_t)M_ * C_];      // fp16 split of y
__device__ __half g_y_lo[(size_t)M_ * C_];
__device__ __half g_wqkvT_h[(size_t)C3_ * C_];  // [N=3C][K=C] single fp16
__device__ __half g_woutT_h[(size_t)C_ * C_];   // [N=C][K=C] single fp16
__device__ int g_ctr[2];                        // persistent-GEMM tile counters

// ---------------- helpers ----------------
__device__ __forceinline__ uint32_t smem_u32(const void* p) {
    return (uint32_t)__cvta_generic_to_shared(p);
}
__device__ __forceinline__ void cp_async16(void* s, const void* g) {
    asm volatile("cp.async.cg.shared.global [%0], [%1], 16;\n"
                 :: "r"(smem_u32(s)), "l"(g));
}
__device__ __forceinline__ void cp_commit() {
    asm volatile("cp.async.commit_group;\n" ::);
}
__device__ __forceinline__ void cp_wait0() {
    asm volatile("cp.async.wait_group 0;\n" ::);
}
__device__ __forceinline__ void mma_f16(float* d, const uint32_t* a, const uint32_t* b) {
    asm volatile(
        "mma.sync.aligned.m16n8k16.row.col.f32.f16.f16.f32 "
        "{%0,%1,%2,%3}, {%4,%5,%6,%7}, {%8,%9}, {%0,%1,%2,%3};\n"
        : "+f"(d[0]), "+f"(d[1]), "+f"(d[2]), "+f"(d[3])
        : "r"(a[0]), "r"(a[1]), "r"(a[2]), "r"(a[3]),
          "r"(b[0]), "r"(b[1]));
}
__device__ __forceinline__ void ldsm_x4(uint32_t* r, uint32_t addr) {
    asm volatile("ldmatrix.sync.aligned.m8n8.x4.shared.b16 {%0,%1,%2,%3}, [%4];"
                 : "=r"(r[0]), "=r"(r[1]), "=r"(r[2]), "=r"(r[3])
                 : "r"(addr));
}
__device__ __forceinline__ void ldsm_x4_trans(uint32_t* r, uint32_t addr) {
    asm volatile("ldmatrix.sync.aligned.m8n8.x4.trans.shared.b16 {%0,%1,%2,%3}, [%4];"
                 : "=r"(r[0]), "=r"(r[1]), "=r"(r[2]), "=r"(r[3])
                 : "r"(addr));
}
// pack two floats into fp16x2 (first arg -> low half)
__device__ __forceinline__ uint32_t pack_f16x2(float lo, float hi) {
    uint32_t r;
    asm("cvt.rn.f16x2.f32 %0, %1, %2;" : "=r"(r) : "f"(hi), "f"(lo));
    return r;
}
__device__ __forceinline__ uint32_t pack_hi_pair_f16(float a, float b,
                                                     float& ra, float& rb) {
    uint32_t w = pack_f16x2(a, b);
    __half2 h = *reinterpret_cast<__half2*>(&w);
    ra = a - __half2float(h.x);
    rb = b - __half2float(h.y);
    return w;
}

// ---------------- fused prep kernel (one launch) ----------------
// blocks [0,256):       split x -> fp16 xhi/xlo (grid-stride)
// blocks [256,3328):    transpose w_qkv -> fp16 (96x32 tiles of 32x32)
// blocks [3328,4352):   transpose w_out -> fp16 (32x32 tiles)
#define PREP_GRID (256 + 3072 + 1024)

__global__ __launch_bounds__(256) void prep_kernel(
    const float* __restrict__ x,
    __half* __restrict__ xhi, __half* __restrict__ xlo,
    const float* __restrict__ wqkv, __half* __restrict__ wq,
    const float* __restrict__ wout, __half* __restrict__ wo)
{
    const int bid = blockIdx.x;
    const int t   = threadIdx.x;
    if (bid == 0 && t == 0) { g_ctr[0] = 0; g_ctr[1] = 0; }

    if (bid < 256) {
        const int n = M_ * C_;
        for (int i = bid * 256 + t; i < n; i += 256 * 256) {
            float v = x[i];
            __half h = __float2half_rn(v);
            xhi[i] = h;
            xlo[i] = __float2half_rn(v - __half2float(h));
        }
        return;
    }

    __shared__ float ts[32][33];
    const int tx = t & 31;
    const int ty = t >> 5;
    const int K  = C_;

    const float* src; __half* dst; int N, tileid, ncols;
    if (bid < 256 + 3072) {
        tileid = bid - 256;  src = wqkv; dst = wq; N = C3_; ncols = 96;
    } else {
        tileid = bid - 3328; src = wout; dst = wo; N = C_;  ncols = 32;
    }
    const int n0 = (tileid % ncols) * 32;
    const int k0 = (tileid / ncols) * 32;
#pragma unroll
    for (int i = 0; i < 4; i++) {
        int k = k0 + ty + i * 8;
        ts[ty + i * 8][tx] = src[(size_t)k * N + n0 + tx];
    }
    __syncthreads();
#pragma unroll
    for (int i = 0; i < 4; i++) {
        int n = n0 + ty + i * 8;
        dst[(size_t)n * K + k0 + tx] = __float2half_rn(ts[tx][ty + i * 8]);
    }
}

// shared GEMM geometry
#define GBM 128
#define GBN 128
#define GBK 32
#define TSTRIDE 20                     // uint32 words per SMEM tile row (80 B)
#define TILE_WORDS (128 * TSTRIDE)
#define GEMM_GRID 304                  // 2 CTAs x 152 SMs

// ================= fp16 2-term persistent GEMM =================
// D = (Ahi + Alo)[M,K] @ B^T + bias; A split fp16, B single fp16 [N][K].
// Output: fp16 hi/lo (Chi != nullptr) or fp32 (Cout).
// 128 threads = 4 warps (2x2), warp tile 64x64.
__global__ __launch_bounds__(128, 2) void gemm_f16x2_kernel(
    const __half* __restrict__ Ahi, const __half* __restrict__ Alo,
    const __half* __restrict__ Bw,
    const float* __restrict__ bias,
    float* __restrict__ Cout,
    __half* __restrict__ Chi, __half* __restrict__ Clo,
    int M, int N, int K, int ctr_slot)
{
    extern __shared__ uint32_t sm[];
    __shared__ int s_next;
    uint32_t* tiles[2][3];   // 0=Ahi 1=Alo 2=B
#pragma unroll
    for (int b = 0; b < 2; b++)
#pragma unroll
        for (int t = 0; t < 3; t++)
            tiles[b][t] = sm + (b * 3 + t) * TILE_WORDS;

    const int tid  = threadIdx.x;
    const int wid  = tid >> 5;
    const int lane = tid & 31;
    const int g    = lane >> 2;
    const int q    = lane & 3;
    const int wm   = (wid & 1) * 64;
    const int wn   = (wid >> 1) * 64;

    const int grp = lane >> 3;
    const int rl  = lane & 7;
    uint32_t aRel[4];
#pragma unroll
    for (int mi = 0; mi < 4; mi++)
        aRel[mi] = (uint32_t)((wm + mi * 16 + (grp & 1) * 8 + rl) * 80
                              + (grp >> 1) * 16);
    uint32_t bRel[4];
#pragma unroll
    for (int ni2 = 0; ni2 < 4; ni2++)
        bRel[ni2] = (uint32_t)((wn + ni2 * 16 + (grp >> 1) * 8 + rl) * 80
                               + (grp & 1) * 16);

    const int ncol    = N / GBN;
    const int n_tiles = (M / GBM) * ncol;
    int ti = blockIdx.x;

    while (ti < n_tiles) {
        const int row0 = (ti / ncol) * GBM;
        const int col0 = (ti % ncol) * GBN;

        float acc[4][8][4];
#pragma unroll
        for (int mi = 0; mi < 4; mi++)
#pragma unroll
            for (int ni = 0; ni < 8; ni++)
#pragma unroll
                for (int r = 0; r < 4; r++) acc[mi][ni][r] = 0.f;

        const __half* srcs[3] = {Ahi, Alo, Bw};
        auto load_tile = [&](int kt, int buf) {
            const int k0 = kt * GBK;
#pragma unroll
            for (int t = 0; t < 3; t++) {
                const __half* base = srcs[t] +
                    (size_t)((t < 2) ? row0 : col0) * K + k0;
#pragma unroll
                for (int it = 0; it < 4; it++) {
                    int idx = tid + it * 128;       // 0..511
                    int r   = idx >> 2;
                    int f   = idx & 3;
                    cp_async16(&tiles[buf][t][r * TSTRIDE + f * 4],
                               base + (size_t)r * K + f * 8);
                }
            }
            cp_commit();
        };

        load_tile(0, 0);
        cp_wait0();
        __syncthreads();

        const int KT = K / GBK;
        for (int kt = 0; kt < KT; kt++) {
            const int buf = kt & 1;
            if (kt + 1 < KT) load_tile(kt + 1, buf ^ 1);

            const uint32_t baseAh = smem_u32(tiles[buf][0]);
            const uint32_t baseAl = smem_u32(tiles[buf][1]);
            const uint32_t baseB  = smem_u32(tiles[buf][2]);

#pragma unroll
            for (int ks = 0; ks < 2; ks++) {
                const uint32_t ko = (uint32_t)ks * 32;
                uint32_t ah[4][4], al[4][4], bf[8][2];
#pragma unroll
                for (int mi = 0; mi < 4; mi++) {
                    ldsm_x4(ah[mi], baseAh + aRel[mi] + ko);
                    ldsm_x4(al[mi], baseAl + aRel[mi] + ko);
                }
#pragma unroll
                for (int ni2 = 0; ni2 < 4; ni2++) {
                    uint32_t t4[4];
                    ldsm_x4(t4, baseB + bRel[ni2] + ko);
                    bf[2*ni2][0] = t4[0]; bf[2*ni2][1] = t4[1];
                    bf[2*ni2+1][0] = t4[2]; bf[2*ni2+1][1] = t4[3];
                }
#pragma unroll
                for (int mi = 0; mi < 4; mi++)
#pragma unroll
                    for (int ni = 0; ni < 8; ni++)
                        mma_f16(acc[mi][ni], ah[mi], bf[ni]);
#pragma unroll
                for (int mi = 0; mi < 4; mi++)
#pragma unroll
                    for (int ni = 0; ni < 8; ni++)
                        mma_f16(acc[mi][ni], al[mi], bf[ni]);
            }

            if (kt + 1 < KT) cp_wait0();
            __syncthreads();
        }

        // ---- epilogue ----
#pragma unroll
        for (int mi = 0; mi < 4; mi++) {
#pragma unroll
            for (int ni = 0; ni < 8; ni++) {
                int r = row0 + wm + mi * 16 + g;
                int c = col0 + wn + ni * 8 + 2 * q;
                float b0 = bias[c], b1 = bias[c + 1];
                float v00 = acc[mi][ni][0] + b0, v01 = acc[mi][ni][1] + b1;
                float v10 = acc[mi][ni][2] + b0, v11 = acc[mi][ni][3] + b1;
                if (Chi) {
                    float r0, r1;
                    uint32_t hw0 = pack_hi_pair_f16(v00, v01, r0, r1);
                    uint32_t lw0 = pack_f16x2(r0, r1);
                    uint32_t hw1 = pack_hi_pair_f16(v10, v11, r0, r1);
                    uint32_t lw1 = pack_f16x2(r0, r1);
                    *(uint32_t*)(Chi + (size_t)r * N + c)       = hw0;
                    *(uint32_t*)(Clo + (size_t)r * N + c)       = lw0;
                    *(uint32_t*)(Chi + (size_t)(r + 8) * N + c) = hw1;
                    *(uint32_t*)(Clo + (size_t)(r + 8) * N + c) = lw1;
                } else {
                    *(float2*)(Cout + (size_t)r * N + c)       = make_float2(v00, v01);
                    *(float2*)(Cout + (size_t)(r + 8) * N + c) = make_float2(v10, v11);
                }
            }
        }

        if (tid == 0) s_next = (int)gridDim.x + atomicAdd(&g_ctr[ctr_slot], 1);
        __syncthreads();
        ti = s_next;
        __syncthreads();
    }
}

// ================= MMA flash attention (fp16, fp32 softmax) ========
// Block: 256 threads = 8 warps, 128 queries of one (b,h). 64-key tiles,
// double-buffered cp.async. Q split fp16 (2-term), K single fp16,
// P split fp16 (2-term), V single fp16. Scale 0.125 applied to S in fp32.
// SMEM (uint32 words): per buffer 4608 = K@0 (2304) + V@2304.
// Q staging uses words 0..9215 (Qhi@0, Qlo@4608) before K/V loads.
// rows: 64 fp16 = 128 B + 16 B pad => 36 words/row.
#define ATT_SMEM (9216 * 4)

__global__ __launch_bounds__(256, 2) void attn_mma_kernel(
    const __half* __restrict__ qkvhi,
    const __half* __restrict__ qkvlo,
    __half* __restrict__ yhi, __half* __restrict__ ylo)
{
    extern __shared__ uint32_t smd[];
    uint32_t* smB[2] = {smd, smd + 4608};

    const int tid  = threadIdx.x;
    const int w    = tid >> 5;
    const int lane = tid & 31;
    const int g    = lane >> 2;
    const int q    = lane & 3;
    const int grp  = lane >> 3;
    const int rl   = lane & 7;
    const int bh   = blockIdx.x;
    const int b    = bh >> 4;
    const int h    = bh & 15;
    const int qt   = (gridDim.y - 1) - blockIdx.y;   // heavy blocks first
    const int qb   = qt * 128;

    // ---- stage Q hi/lo, extract fragments ----
#pragma unroll
    for (int it = 0; it < 8; it++) {
        int idx = tid + it * 256;            // 0..2047
        int arr = idx >> 10;                 // 0=hi,1=lo
        int rem = idx & 1023;
        int row = rem >> 3;
        int ch  = rem & 7;
        const __half* src = (arr ? qkvlo : qkvhi)
            + (size_t)(b * T_ + qb + row) * C3_ + h * HD_ + ch * 8;
        cp_async16(&smd[arr * 4608 + row * 36 + ch * 4], src);
    }
    cp_commit();
    cp_wait0();
    __syncthreads();

    uint32_t qh[4][4], ql[4][4];
    {
        uint32_t qa = smem_u32(&smd[0])
            + (uint32_t)((w * 16 + (grp & 1) * 8 + rl) * 144 + (grp >> 1) * 16);
#pragma unroll
        for (int ks = 0; ks < 4; ks++) {
            ldsm_x4(qh[ks], qa + ks * 32);
            ldsm_x4(ql[ks], qa + 4608 * 4 + ks * 32);
        }
    }
    __syncthreads();   // SMEM free for K/V

    // K/V tile sources (single fp16 = hi array)
    const __half* kv_src[2] = {qkvhi + C_, qkvhi + 2 * C_};
    auto load_tile = [&](int kt, int bufi) {
        const int k0 = kt * 64;
#pragma unroll
        for (int it = 0; it < 4; it++) {
            int idx = tid + it * 256;        // 0..1023
            int arr = idx >> 9;              // 0=K,1=V
            int rem = idx & 511;
            int row = rem >> 3;
            int ch  = rem & 7;
            const __half* src = kv_src[arr]
                + (size_t)(b * T_ + k0 + row) * C3_ + h * HD_ + ch * 8;
            cp_async16(&smB[bufi][arr * 2304 + row * 36 + ch * 4], src);
        }
        cp_commit();
    };

    float o[8][4];
#pragma unroll
    for (int nj = 0; nj < 8; nj++)
#pragma unroll
        for (int c = 0; c < 4; c++) o[nj][c] = 0.f;
    float m0 = -INFINITY, m1 = -INFINITY;
    float l0 = 0.f, l1 = 0.f;

    const int qrow0 = qb + w * 16 + g;
    const int qrow1 = qrow0 + 8;
    const int qmax_w = qb + w * 16 + 15;
    const int kt_max = (qb + 127) >> 6;

    load_tile(0, 0);
    cp_wait0();
    __syncthreads();

    for (int kt = 0; kt <= kt_max; kt++) {
        const int bufi = kt & 1;
        const int k0 = kt * 64;
        if (kt + 1 <= kt_max) load_tile(kt + 1, bufi ^ 1);

        if (k0 <= qmax_w) {
            const uint32_t sb = smem_u32(&smB[bufi][0]);

            // ---- S = Q K^T (2-term fp16) ----
            float s[8][4];
#pragma unroll
            for (int ni2 = 0; ni2 < 4; ni2++) {
#pragma unroll
                for (int c = 0; c < 4; c++) {
                    s[2*ni2][c] = 0.f; s[2*ni2+1][c] = 0.f;
                }
                const uint32_t ka = sb
                    + (uint32_t)((ni2 * 16 + (grp >> 1) * 8 + rl) * 144
                                 + (grp & 1) * 16);
#pragma unroll
                for (int ks = 0; ks < 4; ks++) {
                    uint32_t k4[4];
                    ldsm_x4(k4, ka + ks * 32);
                    mma_f16(s[2*ni2],   qh[ks], k4);
                    mma_f16(s[2*ni2],   ql[ks], k4);
                    mma_f16(s[2*ni2+1], qh[ks], k4 + 2);
                    mma_f16(s[2*ni2+1], ql[ks], k4 + 2);
                }
            }
            // softmax scale (1/sqrt(64)), exact in fp32
#pragma unroll
            for (int ni = 0; ni < 8; ni++)
#pragma unroll
                for (int c = 0; c < 4; c++) s[ni][c] *= 0.125f;

            // ---- causal mask ----
            if (k0 + 63 > qb + w * 16) {
#pragma unroll
                for (int ni = 0; ni < 8; ni++) {
                    int key = k0 + 8 * ni + 2 * q;
                    s[ni][0] = (key     <= qrow0) ? s[ni][0] : -INFINITY;
                    s[ni][1] = (key + 1 <= qrow0) ? s[ni][1] : -INFINITY;
                    s[ni][2] = (key     <= qrow1) ? s[ni][2] : -INFINITY;
                    s[ni][3] = (key + 1 <= qrow1) ? s[ni][3] : -INFINITY;
                }
            }

            // ---- online softmax ----
            float mx0 = s[0][0], mx1 = s[0][2];
#pragma unroll
            for (int ni = 0; ni < 8; ni++) {
                mx0 = fmaxf(mx0, fmaxf(s[ni][0], s[ni][1]));
                mx1 = fmaxf(mx1, fmaxf(s[ni][2], s[ni][3]));
            }
            mx0 = fmaxf(mx0, __shfl_xor_sync(0xffffffff, mx0, 1));
            mx0 = fmaxf(mx0, __shfl_xor_sync(0xffffffff, mx0, 2));
            mx1 = fmaxf(mx1, __shfl_xor_sync(0xffffffff, mx1, 1));
            mx1 = fmaxf(mx1, __shfl_xor_sync(0xffffffff, mx1, 2));

            float mn0 = fmaxf(m0, mx0), mn1 = fmaxf(m1, mx1);
            float al0 = __expf(m0 - mn0), al1 = __expf(m1 - mn1);
            m0 = mn0; m1 = mn1;
            l0 *= al0; l1 *= al1;
#pragma unroll
            for (int nj = 0; nj < 8; nj++) {
                o[nj][0] *= al0; o[nj][1] *= al0;
                o[nj][2] *= al1; o[nj][3] *= al1;
            }

            // ---- per k16 step: pack P hi/lo, O += P V (2-term) ----
#pragma unroll
            for (int ks = 0; ks < 4; ks++) {
                uint32_t af_hi[4], af_lo[4];
#pragma unroll
                for (int half = 0; half < 2; half++) {
                    const int ni = 2 * ks + half;
                    float p0 = __expf(s[ni][0] - mn0);
                    float p1 = __expf(s[ni][1] - mn0);
                    float p2 = __expf(s[ni][2] - mn1);
                    float p3 = __expf(s[ni][3] - mn1);
                    l0 += p0 + p1;
                    l1 += p2 + p3;
                    float r0, r1, r2, r3;
                    af_hi[2*half]     = pack_hi_pair_f16(p0, p1, r0, r1);
                    af_lo[2*half]     = pack_f16x2(r0, r1);
                    af_hi[2*half + 1] = pack_hi_pair_f16(p2, p3, r2, r3);
                    af_lo[2*half + 1] = pack_f16x2(r2, r3);
                }
                const uint32_t va = sb + 2304 * 4
                    + (uint32_t)((ks * 16 + (grp & 1) * 8 + rl) * 144
                                 + (grp >> 1) * 16);
#pragma unroll
                for (int nj2 = 0; nj2 < 4; nj2++) {
                    uint32_t v4[4];
                    ldsm_x4_trans(v4, va + nj2 * 32);
                    mma_f16(o[2*nj2],   af_hi, v4);
                    mma_f16(o[2*nj2],   af_lo, v4);
                    mma_f16(o[2*nj2+1], af_hi, v4 + 2);
                    mma_f16(o[2*nj2+1], af_lo, v4 + 2);
                }
            }
        }

        cp_wait0();
        __syncthreads();
    }

    // ---- epilogue ----
    l0 += __shfl_xor_sync(0xffffffff, l0, 1);
    l0 += __shfl_xor_sync(0xffffffff, l0, 2);
    l1 += __shfl_xor_sync(0xffffffff, l1, 1);
    l1 += __shfl_xor_sync(0xffffffff, l1, 2);
    const float inv0 = 1.f / l0;
    const float inv1 = 1.f / l1;

    __half* yh0 = yhi + (size_t)(b * T_ + qrow0) * C_ + h * HD_;
    __half* yl0 = ylo + (size_t)(b * T_ + qrow0) * C_ + h * HD_;
    __half* yh1 = yhi + (size_t)(b * T_ + qrow1) * C_ + h * HD_;
    __half* yl1 = ylo + (size_t)(b * T_ + qrow1) * C_ + h * HD_;
#pragma unroll
    for (int nj = 0; nj < 8; nj++) {
        int c = 8 * nj + 2 * q;
        float a0 = o[nj][0] * inv0, a1 = o[nj][1] * inv0;
        float a2 = o[nj][2] * inv1, a3 = o[nj][3] * inv1;
        float r0, r1, r2, r3;
        uint32_t h01 = pack_hi_pair_f16(a0, a1, r0, r1);
        uint32_t h23 = pack_hi_pair_f16(a2, a3, r2, r3);
        *(uint32_t*)(yh0 + c) = h01;
        *(uint32_t*)(yl0 + c) = pack_f16x2(r0, r1);
        *(uint32_t*)(yh1 + c) = h23;
        *(uint32_t*)(yl1 + c) = pack_f16x2(r2, r3);
    }
}

// ---------------- launch ----------------
extern "C" void kernel_launch(void* const* d_in, const int* in_sizes, int n_in,
                              void* d_out, int out_size)
{
    const float* x     = (const float*)d_in[0];
    const float* w_qkv = (const float*)d_in[1];
    const float* b_qkv = (const float*)d_in[2];
    const float* w_out = (const float*)d_in[3];
    const float* b_out = (const float*)d_in[4];
    float* out = (float*)d_out;

    __half *qkvhi, *qkvlo, *xhi, *xlo, *yhi, *ylo, *wq, *wo;
    cudaGetSymbolAddress((void**)&qkvhi, g_qkv_hi);
    cudaGetSymbolAddress((void**)&qkvlo, g_qkv_lo);
    cudaGetSymbolAddress((void**)&xhi, g_x_hi);
    cudaGetSymbolAddress((void**)&xlo, g_x_lo);
    cudaGetSymbolAddress((void**)&yhi, g_y_hi);
    cudaGetSymbolAddress((void**)&ylo, g_y_lo);
    cudaGetSymbolAddress((void**)&wq, g_wqkvT_h);
    cudaGetSymbolAddress((void**)&wo, g_woutT_h);

    static bool attr_set = false;
    if (!attr_set) {
        cudaFuncSetAttribute(gemm_f16x2_kernel,
                             cudaFuncAttributeMaxDynamicSharedMemorySize,
                             6 * TILE_WORDS * 4);
        cudaFuncSetAttribute(attn_mma_kernel,
                             cudaFuncAttributeMaxDynamicSharedMemorySize,
                             ATT_SMEM);
        attr_set = true;
    }
    const int gemm_smem = 6 * TILE_WORDS * 4;   // 61440 B

    // 0) fused prep
    prep_kernel<<<PREP_GRID, 256>>>(x, xhi, xlo, w_qkv, wq, w_out, wo);

    // 1) qkv = x @ w_qkv + b_qkv  (fp16 2-term)  -> fp16 hi/lo
    gemm_f16x2_kernel<<<GEMM_GRID, 128, gemm_smem>>>(
        xhi, xlo, wq, b_qkv, nullptr, qkvhi, qkvlo, M_, C3_, C_, 0);

    // 2) causal attention -> y (fp16 hi/lo)
    {
        dim3 grid(B_ * H_, T_ / 128);
        attn_mma_kernel<<<grid, 256, ATT_SMEM>>>(qkvhi, qkvlo, yhi, ylo);
    }

    // 3) out = y @ w_out + b_out  (fp16 2-term)  -> fp32
    gemm_f16x2_kernel<<<GEMM_GRID, 128, gemm_smem>>>(
        yhi, ylo, wo, b_out, out, nullptr, nullptr, M_, C_, C_, 1);
}

// round 13
// speedup vs baseline: 2.4707x; 1.7053x over previous
#include <cuda_runtime.h>
#include <cuda_fp16.h>
#include <math.h>
#include <stdint.h>

// Problem dims (fixed by the dataset)
#define B_   2
#define T_   2048
#define C_   1024
#define H_   16
#define HD_  64
#define C3_  (3*C_)
#define M_   (B_*T_)          // 4096 rows

// ---------------- scratch (no cudaMalloc allowed) ----------------
__device__ __half g_qkv[(size_t)M_ * C3_];      // fp16 qkv
__device__ __half g_x  [(size_t)M_ * C_];       // fp16 x
__device__ __half g_y  [(size_t)M_ * C_];       // fp16 y
__device__ __half g_wqkvT[(size_t)C3_ * C_];    // [N=3C][K=C] fp16
__device__ __half g_woutT[(size_t)C_ * C_];     // [N=C][K=C] fp16
__device__ int g_ctr[2];                        // persistent-GEMM tile counters

// ---------------- helpers ----------------
__device__ __forceinline__ uint32_t smem_u32(const void* p) {
    return (uint32_t)__cvta_generic_to_shared(p);
}
__device__ __forceinline__ void cp_async16(void* s, const void* g) {
    asm volatile("cp.async.cg.shared.global [%0], [%1], 16;\n"
                 :: "r"(smem_u32(s)), "l"(g));
}
__device__ __forceinline__ void cp_commit() {
    asm volatile("cp.async.commit_group;\n" ::);
}
__device__ __forceinline__ void cp_wait0() {
    asm volatile("cp.async.wait_group 0;\n" ::);
}
__device__ __forceinline__ void mma_f16(float* d, const uint32_t* a, const uint32_t* b) {
    asm volatile(
        "mma.sync.aligned.m16n8k16.row.col.f32.f16.f16.f32 "
        "{%0,%1,%2,%3}, {%4,%5,%6,%7}, {%8,%9}, {%0,%1,%2,%3};\n"
        : "+f"(d[0]), "+f"(d[1]), "+f"(d[2]), "+f"(d[3])
        : "r"(a[0]), "r"(a[1]), "r"(a[2]), "r"(a[3]),
          "r"(b[0]), "r"(b[1]));
}
__device__ __forceinline__ void ldsm_x4(uint32_t* r, uint32_t addr) {
    asm volatile("ldmatrix.sync.aligned.m8n8.x4.shared.b16 {%0,%1,%2,%3}, [%4];"
                 : "=r"(r[0]), "=r"(r[1]), "=r"(r[2]), "=r"(r[3])
                 : "r"(addr));
}
__device__ __forceinline__ void ldsm_x4_trans(uint32_t* r, uint32_t addr) {
    asm volatile("ldmatrix.sync.aligned.m8n8.x4.trans.shared.b16 {%0,%1,%2,%3}, [%4];"
                 : "=r"(r[0]), "=r"(r[1]), "=r"(r[2]), "=r"(r[3])
                 : "r"(addr));
}
// pack two floats into fp16x2 (first arg -> low half)
__device__ __forceinline__ uint32_t pack_f16x2(float lo, float hi) {
    uint32_t r;
    asm("cvt.rn.f16x2.f32 %0, %1, %2;" : "=r"(r) : "f"(hi), "f"(lo));
    return r;
}

// ---------------- fused prep kernel (one launch) ----------------
// blocks [0,256):       convert x -> fp16 (grid-stride)
// blocks [256,3328):    transpose w_qkv -> fp16 (96x32 tiles of 32x32)
// blocks [3328,4352):   transpose w_out -> fp16 (32x32 tiles)
#define PREP_GRID (256 + 3072 + 1024)

__global__ __launch_bounds__(256) void prep_kernel(
    const float* __restrict__ x, __half* __restrict__ xh,
    const float* __restrict__ wqkv, __half* __restrict__ wq,
    const float* __restrict__ wout, __half* __restrict__ wo)
{
    const int bid = blockIdx.x;
    const int t   = threadIdx.x;
    if (bid == 0 && t == 0) { g_ctr[0] = 0; g_ctr[1] = 0; }

    if (bid < 256) {
        const int n = M_ * C_;
        for (int i = bid * 256 + t; i < n; i += 256 * 256)
            xh[i] = __float2half_rn(x[i]);
        return;
    }

    __shared__ float ts[32][33];
    const int tx = t & 31;
    const int ty = t >> 5;
    const int K  = C_;

    const float* src; __half* dst; int N, tileid, ncols;
    if (bid < 256 + 3072) {
        tileid = bid - 256;  src = wqkv; dst = wq; N = C3_; ncols = 96;
    } else {
        tileid = bid - 3328; src = wout; dst = wo; N = C_;  ncols = 32;
    }
    const int n0 = (tileid % ncols) * 32;
    const int k0 = (tileid / ncols) * 32;
#pragma unroll
    for (int i = 0; i < 4; i++) {
        int k = k0 + ty + i * 8;
        ts[ty + i * 8][tx] = src[(size_t)k * N + n0 + tx];
    }
    __syncthreads();
#pragma unroll
    for (int i = 0; i < 4; i++) {
        int n = n0 + ty + i * 8;
        dst[(size_t)n * K + k0 + tx] = __float2half_rn(ts[tx][ty + i * 8]);
    }
}

// shared GEMM geometry
#define GBM 128
#define GBN 128
#define GBK 32
#define TSTRIDE 20                     // uint32 words per SMEM tile row (80 B)
#define TILE_WORDS (128 * TSTRIDE)
#define GEMM_GRID 304                  // 2 CTAs x 152 SMs

// ================= fp16 persistent GEMM =================
// D = A[M,K] @ B^T + bias; A fp16, B fp16 [N][K], fp32 accumulate.
// Output: fp16 (Ch != nullptr) or fp32 (Cout).
// 128 threads = 4 warps (2x2), warp tile 64x64.
__global__ __launch_bounds__(128, 2) void gemm_f16_kernel(
    const __half* __restrict__ A, const __half* __restrict__ Bw,
    const float* __restrict__ bias,
    float* __restrict__ Cout, __half* __restrict__ Ch,
    int M, int N, int K, int ctr_slot)
{
    extern __shared__ uint32_t sm[];
    __shared__ int s_next;
    uint32_t* tiles[2][2];   // 0=A 1=B
#pragma unroll
    for (int b = 0; b < 2; b++)
#pragma unroll
        for (int t = 0; t < 2; t++)
            tiles[b][t] = sm + (b * 2 + t) * TILE_WORDS;

    const int tid  = threadIdx.x;
    const int wid  = tid >> 5;
    const int lane = tid & 31;
    const int g    = lane >> 2;
    const int q    = lane & 3;
    const int wm   = (wid & 1) * 64;
    const int wn   = (wid >> 1) * 64;

    const int grp = lane >> 3;
    const int rl  = lane & 7;
    uint32_t aRel[4];
#pragma unroll
    for (int mi = 0; mi < 4; mi++)
        aRel[mi] = (uint32_t)((wm + mi * 16 + (grp & 1) * 8 + rl) * 80
                              + (grp >> 1) * 16);
    uint32_t bRel[4];
#pragma unroll
    for (int ni2 = 0; ni2 < 4; ni2++)
        bRel[ni2] = (uint32_t)((wn + ni2 * 16 + (grp >> 1) * 8 + rl) * 80
                               + (grp & 1) * 16);

    const int ncol    = N / GBN;
    const int n_tiles = (M / GBM) * ncol;
    int ti = blockIdx.x;

    while (ti < n_tiles) {
        const int row0 = (ti / ncol) * GBM;
        const int col0 = (ti % ncol) * GBN;

        float acc[4][8][4];
#pragma unroll
        for (int mi = 0; mi < 4; mi++)
#pragma unroll
            for (int ni = 0; ni < 8; ni++)
#pragma unroll
                for (int r = 0; r < 4; r++) acc[mi][ni][r] = 0.f;

        const __half* srcs[2] = {A, Bw};
        auto load_tile = [&](int kt, int buf) {
            const int k0 = kt * GBK;
#pragma unroll
            for (int t = 0; t < 2; t++) {
                const __half* base = srcs[t] +
                    (size_t)((t < 1) ? row0 : col0) * K + k0;
#pragma unroll
                for (int it = 0; it < 4; it++) {
                    int idx = tid + it * 128;       // 0..511
                    int r   = idx >> 2;
                    int f   = idx & 3;
                    cp_async16(&tiles[buf][t][r * TSTRIDE + f * 4],
                               base + (size_t)r * K + f * 8);
                }
            }
            cp_commit();
        };

        load_tile(0, 0);
        cp_wait0();
        __syncthreads();

        const int KT = K / GBK;
        for (int kt = 0; kt < KT; kt++) {
            const int buf = kt & 1;
            if (kt + 1 < KT) load_tile(kt + 1, buf ^ 1);

            const uint32_t baseA = smem_u32(tiles[buf][0]);
            const uint32_t baseB = smem_u32(tiles[buf][1]);

#pragma unroll
            for (int ks = 0; ks < 2; ks++) {
                const uint32_t ko = (uint32_t)ks * 32;
                uint32_t af[4][4], bf[8][2];
#pragma unroll
                for (int mi = 0; mi < 4; mi++)
                    ldsm_x4(af[mi], baseA + aRel[mi] + ko);
#pragma unroll
                for (int ni2 = 0; ni2 < 4; ni2++) {
                    uint32_t t4[4];
                    ldsm_x4(t4, baseB + bRel[ni2] + ko);
                    bf[2*ni2][0] = t4[0]; bf[2*ni2][1] = t4[1];
                    bf[2*ni2+1][0] = t4[2]; bf[2*ni2+1][1] = t4[3];
                }
#pragma unroll
                for (int mi = 0; mi < 4; mi++)
#pragma unroll
                    for (int ni = 0; ni < 8; ni++)
                        mma_f16(acc[mi][ni], af[mi], bf[ni]);
            }

            if (kt + 1 < KT) cp_wait0();
            __syncthreads();
        }

        // ---- epilogue ----
#pragma unroll
        for (int mi = 0; mi < 4; mi++) {
#pragma unroll
            for (int ni = 0; ni < 8; ni++) {
                int r = row0 + wm + mi * 16 + g;
                int c = col0 + wn + ni * 8 + 2 * q;
                float b0 = bias[c], b1 = bias[c + 1];
                float v00 = acc[mi][ni][0] + b0, v01 = acc[mi][ni][1] + b1;
                float v10 = acc[mi][ni][2] + b0, v11 = acc[mi][ni][3] + b1;
                if (Ch) {
                    *(uint32_t*)(Ch + (size_t)r * N + c)       = pack_f16x2(v00, v01);
                    *(uint32_t*)(Ch + (size_t)(r + 8) * N + c) = pack_f16x2(v10, v11);
                } else {
                    *(float2*)(Cout + (size_t)r * N + c)       = make_float2(v00, v01);
                    *(float2*)(Cout + (size_t)(r + 8) * N + c) = make_float2(v10, v11);
                }
            }
        }

        if (tid == 0) s_next = (int)gridDim.x + atomicAdd(&g_ctr[ctr_slot], 1);
        __syncthreads();
        ti = s_next;
        __syncthreads();
    }
}

// ================= MMA flash attention (fp16, fp32 softmax) ========
// Block: 256 threads = 8 warps, 128 queries of one (b,h). 64-key tiles,
// double-buffered cp.async. Single fp16 Q,K,P,V; fp32 accumulate/softmax.
// Scale 0.125 applied to S in fp32 (exact).
// SMEM (uint32 words): per buffer 4608 = K@0 (2304) + V@2304; 2 buffers.
// Q staging reuses words 0..4607 before the K/V loop. 36 words/row.
#define ATT_SMEM (9216 * 4)

__global__ __launch_bounds__(256, 2) void attn_mma_kernel(
    const __half* __restrict__ qkv, __half* __restrict__ y)
{
    extern __shared__ uint32_t smd[];
    uint32_t* smB[2] = {smd, smd + 4608};

    const int tid  = threadIdx.x;
    const int w    = tid >> 5;
    const int lane = tid & 31;
    const int g    = lane >> 2;
    const int q    = lane & 3;
    const int grp  = lane >> 3;
    const int rl   = lane & 7;
    const int bh   = blockIdx.x;
    const int b    = bh >> 4;
    const int h    = bh & 15;
    const int qt   = (gridDim.y - 1) - blockIdx.y;   // heavy blocks first
    const int qb   = qt * 128;

    // ---- stage Q, extract fragments ----
#pragma unroll
    for (int it = 0; it < 4; it++) {
        int idx = tid + it * 256;            // 0..1023
        int row = idx >> 3;
        int ch  = idx & 7;
        const __half* src = qkv
            + (size_t)(b * T_ + qb + row) * C3_ + h * HD_ + ch * 8;
        cp_async16(&smd[row * 36 + ch * 4], src);
    }
    cp_commit();
    cp_wait0();
    __syncthreads();

    uint32_t qf[4][4];
    {
        uint32_t qa = smem_u32(&smd[0])
            + (uint32_t)((w * 16 + (grp & 1) * 8 + rl) * 144 + (grp >> 1) * 16);
#pragma unroll
        for (int ks = 0; ks < 4; ks++)
            ldsm_x4(qf[ks], qa + ks * 32);
    }
    __syncthreads();   // SMEM free for K/V

    const __half* kv_src[2] = {qkv + C_, qkv + 2 * C_};
    auto load_tile = [&](int kt, int bufi) {
        const int k0 = kt * 64;
#pragma unroll
        for (int it = 0; it < 4; it++) {
            int idx = tid + it * 256;        // 0..1023
            int arr = idx >> 9;              // 0=K,1=V
            int rem = idx & 511;
            int row = rem >> 3;
            int ch  = rem & 7;
            const __half* src = kv_src[arr]
                + (size_t)(b * T_ + k0 + row) * C3_ + h * HD_ + ch * 8;
            cp_async16(&smB[bufi][arr * 2304 + row * 36 + ch * 4], src);
        }
        cp_commit();
    };

    float o[8][4];
#pragma unroll
    for (int nj = 0; nj < 8; nj++)
#pragma unroll
        for (int c = 0; c < 4; c++) o[nj][c] = 0.f;
    float m0 = -INFINITY, m1 = -INFINITY;
    float l0 = 0.f, l1 = 0.f;

    const int qrow0 = qb + w * 16 + g;
    const int qrow1 = qrow0 + 8;
    const int qmax_w = qb + w * 16 + 15;
    const int kt_max = (qb + 127) >> 6;

    load_tile(0, 0);
    cp_wait0();
    __syncthreads();

    for (int kt = 0; kt <= kt_max; kt++) {
        const int bufi = kt & 1;
        const int k0 = kt * 64;
        if (kt + 1 <= kt_max) load_tile(kt + 1, bufi ^ 1);

        if (k0 <= qmax_w) {
            const uint32_t sb = smem_u32(&smB[bufi][0]);

            // ---- S = Q K^T ----
            float s[8][4];
#pragma unroll
            for (int ni2 = 0; ni2 < 4; ni2++) {
#pragma unroll
                for (int c = 0; c < 4; c++) {
                    s[2*ni2][c] = 0.f; s[2*ni2+1][c] = 0.f;
                }
                const uint32_t ka = sb
                    + (uint32_t)((ni2 * 16 + (grp >> 1) * 8 + rl) * 144
                                 + (grp & 1) * 16);
#pragma unroll
                for (int ks = 0; ks < 4; ks++) {
                    uint32_t k4[4];
                    ldsm_x4(k4, ka + ks * 32);
                    mma_f16(s[2*ni2],   qf[ks], k4);
                    mma_f16(s[2*ni2+1], qf[ks], k4 + 2);
                }
            }
            // softmax scale (1/sqrt(64)), exact in fp32
#pragma unroll
            for (int ni = 0; ni < 8; ni++)
#pragma unroll
                for (int c = 0; c < 4; c++) s[ni][c] *= 0.125f;

            // ---- causal mask ----
            if (k0 + 63 > qb + w * 16) {
#pragma unroll
                for (int ni = 0; ni < 8; ni++) {
                    int key = k0 + 8 * ni + 2 * q;
                    s[ni][0] = (key     <= qrow0) ? s[ni][0] : -INFINITY;
                    s[ni][1] = (key + 1 <= qrow0) ? s[ni][1] : -INFINITY;
                    s[ni][2] = (key     <= qrow1) ? s[ni][2] : -INFINITY;
                    s[ni][3] = (key + 1 <= qrow1) ? s[ni][3] : -INFINITY;
                }
            }

            // ---- online softmax ----
            float mx0 = s[0][0], mx1 = s[0][2];
#pragma unroll
            for (int ni = 0; ni < 8; ni++) {
                mx0 = fmaxf(mx0, fmaxf(s[ni][0], s[ni][1]));
                mx1 = fmaxf(mx1, fmaxf(s[ni][2], s[ni][3]));
            }
            mx0 = fmaxf(mx0, __shfl_xor_sync(0xffffffff, mx0, 1));
            mx0 = fmaxf(mx0, __shfl_xor_sync(0xffffffff, mx0, 2));
            mx1 = fmaxf(mx1, __shfl_xor_sync(0xffffffff, mx1, 1));
            mx1 = fmaxf(mx1, __shfl_xor_sync(0xffffffff, mx1, 2));

            float mn0 = fmaxf(m0, mx0), mn1 = fmaxf(m1, mx1);
            float al0 = __expf(m0 - mn0), al1 = __expf(m1 - mn1);
            m0 = mn0; m1 = mn1;
            l0 *= al0; l1 *= al1;
#pragma unroll
            for (int nj = 0; nj < 8; nj++) {
                o[nj][0] *= al0; o[nj][1] *= al0;
                o[nj][2] *= al1; o[nj][3] *= al1;
            }

            // ---- per k16 step: pack P (single fp16), O += P V ----
#pragma unroll
            for (int ks = 0; ks < 4; ks++) {
                uint32_t af[4];
#pragma unroll
                for (int half = 0; half < 2; half++) {
                    const int ni = 2 * ks + half;
                    float p0 = __expf(s[ni][0] - mn0);
                    float p1 = __expf(s[ni][1] - mn0);
                    float p2 = __expf(s[ni][2] - mn1);
                    float p3 = __expf(s[ni][3] - mn1);
                    l0 += p0 + p1;
                    l1 += p2 + p3;
                    af[2*half]     = pack_f16x2(p0, p1);
                    af[2*half + 1] = pack_f16x2(p2, p3);
                }
                const uint32_t va = sb + 2304 * 4
                    + (uint32_t)((ks * 16 + (grp & 1) * 8 + rl) * 144
                                 + (grp >> 1) * 16);
#pragma unroll
                for (int nj2 = 0; nj2 < 4; nj2++) {
                    uint32_t v4[4];
                    ldsm_x4_trans(v4, va + nj2 * 32);
                    mma_f16(o[2*nj2],   af, v4);
                    mma_f16(o[2*nj2+1], af, v4 + 2);
                }
            }
        }

        cp_wait0();
        __syncthreads();
    }

    // ---- epilogue ----
    l0 += __shfl_xor_sync(0xffffffff, l0, 1);
    l0 += __shfl_xor_sync(0xffffffff, l0, 2);
    l1 += __shfl_xor_sync(0xffffffff, l1, 1);
    l1 += __shfl_xor_sync(0xffffffff, l1, 2);
    const float inv0 = 1.f / l0;
    const float inv1 = 1.f / l1;

    __half* y0 = y + (size_t)(b * T_ + qrow0) * C_ + h * HD_;
    __half* y1 = y + (size_t)(b * T_ + qrow1) * C_ + h * HD_;
#pragma unroll
    for (int nj = 0; nj < 8; nj++) {
        int c = 8 * nj + 2 * q;
        *(uint32_t*)(y0 + c) = pack_f16x2(o[nj][0] * inv0, o[nj][1] * inv0);
        *(uint32_t*)(y1 + c) = pack_f16x2(o[nj][2] * inv1, o[nj][3] * inv1);
    }
}

// ---------------- launch ----------------
extern "C" void kernel_launch(void* const* d_in, const int* in_sizes, int n_in,
                              void* d_out, int out_size)
{
    const float* x     = (const float*)d_in[0];
    const float* w_qkv = (const float*)d_in[1];
    const float* b_qkv = (const float*)d_in[2];
    const float* w_out = (const float*)d_in[3];
    const float* b_out = (const float*)d_in[4];
    float* out = (float*)d_out;

    __half *qkvp, *xh, *yh, *wq, *wo;
    cudaGetSymbolAddress((void**)&qkvp, g_qkv);
    cudaGetSymbolAddress((void**)&xh, g_x);
    cudaGetSymbolAddress((void**)&yh, g_y);
    cudaGetSymbolAddress((void**)&wq, g_wqkvT);
    cudaGetSymbolAddress((void**)&wo, g_woutT);

    static bool attr_set = false;
    if (!attr_set) {
        cudaFuncSetAttribute(gemm_f16_kernel,
                             cudaFuncAttributeMaxDynamicSharedMemorySize,
                             4 * TILE_WORDS * 4);
        cudaFuncSetAttribute(attn_mma_kernel,
                             cudaFuncAttributeMaxDynamicSharedMemorySize,
                             ATT_SMEM);
        attr_set = true;
    }
    const int gemm_smem = 4 * TILE_WORDS * 4;   // 40960 B

    // 0) fused prep: convert x, transpose+convert both weights
    prep_kernel<<<PREP_GRID, 256>>>(x, xh, w_qkv, wq, w_out, wo);

    // 1) qkv = x @ w_qkv + b_qkv  -> fp16
    gemm_f16_kernel<<<GEMM_GRID, 128, gemm_smem>>>(
        xh, wq, b_qkv, nullptr, qkvp, M_, C3_, C_, 0);

    // 2) causal attention -> y (fp16)
    {
        dim3 grid(B_ * H_, T_ / 128);
        attn_mma_kernel<<<grid, 256, ATT_SMEM>>>(qkvp, yh);
    }

    // 3) out = y @ w_out + b_out  -> fp32
    gemm_f16_kernel<<<GEMM_GRID, 128, gemm_smem>>>(
        yh, wo, b_out, out, nullptr, M_, C_, C_, 1);
}